// round 1
// baseline (speedup 1.0000x reference)
#include <cuda_runtime.h>
#include <math.h>

#define B_   4
#define L_   1024
#define DM   512
#define DI   1024
#define DS   32
#define DR   32
#define DBCW 96
#define NROWS (B_ * L_)   // 4096

// ---------------- scratch (device globals; no runtime allocation) -----------
__device__ float g_XZ[NROWS * 2 * DI];    // xm = cols [0,1024), z = cols [1024,2048)
__device__ float g_U[NROWS * DI];         // silu(conv(xm))
__device__ float g_DBC[NROWS * DBCW];     // dt | B | C
__device__ float g_DELTA[NROWS * DI];     // softplus(dt @ dt_proj^T + b)
__device__ float g_YACT[NROWS * DI];      // (scan_y + u*D) * silu(z)
__device__ float g_Y2[NROWS * DM];        // yact @ out_proj^T
__device__ float g_YN[NROWS * DM];        // layernorm(y2)

// snake permutation for H=W=32, mode 'tl_row'
__device__ __forceinline__ int permi(int i) {
    int r = i >> 5, c = i & 31;
    int col = (r & 1) ? (31 - c) : c;
    return (r << 5) | col;
}

__device__ __forceinline__ float siluf(float x) {
    return x / (1.0f + expf(-x));
}
__device__ __forceinline__ float softplusf(float x) {
    return (x > 20.0f) ? x : log1pf(expf(x));
}
__device__ __forceinline__ float geluf(float x) {
    return 0.5f * x * (1.0f + erff(x * 0.70710678118654752f));
}

// ---------------- generic tiled SGEMM: C = A(MxK) * W(NxK)^T -----------------
// MODE 0: plain store to C (row stride ldc)
// MODE 1: softplus(acc + bias[n]) -> C
// MODE 2: gelu(acc + bias[n]) + tokens[permuted row] -> d_out at permuted row
// PERMA : A row m reads physical row (b*1024 + perm(i))  (folds token permute)
template<int MODE, bool PERMA>
__global__ __launch_bounds__(256)
void gemm_kernel(const float* __restrict__ A, int lda,
                 const float* __restrict__ W,
                 float* __restrict__ C, int ldc,
                 int M, int N, int K,
                 const float* __restrict__ bias,
                 const float* __restrict__ tokens)
{
    __shared__ float As[8][128];
    __shared__ float Bs[8][128];

    const int tid = threadIdx.x;           // 256 threads
    const int tx = tid & 15;               // 0..15
    const int ty = tid >> 4;               // 0..15

    const int loadRow = tid >> 1;          // 0..127
    const int loadK   = (tid & 1) * 4;     // 0 or 4

    // A load pointer (row = blockIdx.y*128 + loadRow, maybe permuted)
    int m_load = blockIdx.y * 128 + loadRow;
    int arow = m_load;
    if (PERMA) {
        int b = m_load >> 10, i = m_load & 1023;
        arow = (b << 10) + permi(i);
    }
    const float* Aptr = A + (size_t)arow * lda;

    // W load pointer (row n)
    int n_load = blockIdx.x * 128 + loadRow;
    const float* Wptr = W + (size_t)n_load * K;
    const bool wvalid = (n_load < N);

    float acc[8][8];
#pragma unroll
    for (int i = 0; i < 8; i++)
#pragma unroll
        for (int j = 0; j < 8; j++) acc[i][j] = 0.0f;

    for (int kt = 0; kt < K; kt += 8) {
        float4 av = *(const float4*)(Aptr + kt + loadK);
        float4 wv = make_float4(0.f, 0.f, 0.f, 0.f);
        if (wvalid) wv = *(const float4*)(Wptr + kt + loadK);

        As[loadK + 0][loadRow] = av.x;
        As[loadK + 1][loadRow] = av.y;
        As[loadK + 2][loadRow] = av.z;
        As[loadK + 3][loadRow] = av.w;
        Bs[loadK + 0][loadRow] = wv.x;
        Bs[loadK + 1][loadRow] = wv.y;
        Bs[loadK + 2][loadRow] = wv.z;
        Bs[loadK + 3][loadRow] = wv.w;
        __syncthreads();

#pragma unroll
        for (int kk = 0; kk < 8; kk++) {
            float4 a0 = *(const float4*)&As[kk][ty * 8];
            float4 a1 = *(const float4*)&As[kk][ty * 8 + 4];
            float4 b0 = *(const float4*)&Bs[kk][tx * 8];
            float4 b1 = *(const float4*)&Bs[kk][tx * 8 + 4];
            float ar[8] = {a0.x, a0.y, a0.z, a0.w, a1.x, a1.y, a1.z, a1.w};
            float br[8] = {b0.x, b0.y, b0.z, b0.w, b1.x, b1.y, b1.z, b1.w};
#pragma unroll
            for (int i = 0; i < 8; i++)
#pragma unroll
                for (int j = 0; j < 8; j++)
                    acc[i][j] = fmaf(ar[i], br[j], acc[i][j]);
        }
        __syncthreads();
    }

    const int m0 = blockIdx.y * 128 + ty * 8;
    const int n0 = blockIdx.x * 128 + tx * 8;

#pragma unroll
    for (int i = 0; i < 8; i++) {
        int m = m0 + i;
        if (MODE == 2) {
            int b = m >> 10, ii = m & 1023;
            int row_out = (b << 10) + permi(ii);
#pragma unroll
            for (int j = 0; j < 8; j++) {
                int n = n0 + j;
                if (n < N) {
                    float v = geluf(acc[i][j] + bias[n]);
                    size_t idx = (size_t)row_out * ldc + n;
                    C[idx] = v + tokens[idx];
                }
            }
        } else {
#pragma unroll
            for (int j = 0; j < 8; j++) {
                int n = n0 + j;
                if (n < N) {
                    float v = acc[i][j];
                    if (MODE == 1) v = softplusf(v + bias[n]);
                    C[(size_t)m * ldc + n] = v;
                }
            }
        }
    }
}

// ---------------- depthwise causal conv (k=4, left pad 3) + bias + silu ------
__global__ void conv_silu_kernel(const float* __restrict__ conv_w,
                                 const float* __restrict__ conv_b)
{
    const int d  = threadIdx.x;            // 0..1023
    const int bt = blockIdx.x;             // 0..4095
    const int b = bt >> 10, t = bt & 1023;

    float w0 = conv_w[d * 4 + 0];
    float w1 = conv_w[d * 4 + 1];
    float w2 = conv_w[d * 4 + 2];
    float w3 = conv_w[d * 4 + 3];

    const size_t base = ((size_t)(b << 10)) * 2048 + d;
    float acc = conv_b[d];
    if (t - 3 >= 0) acc = fmaf(w0, g_XZ[base + (size_t)(t - 3) * 2048], acc);
    if (t - 2 >= 0) acc = fmaf(w1, g_XZ[base + (size_t)(t - 2) * 2048], acc);
    if (t - 1 >= 0) acc = fmaf(w2, g_XZ[base + (size_t)(t - 1) * 2048], acc);
    acc = fmaf(w3, g_XZ[base + (size_t)t * 2048], acc);

    g_U[(size_t)bt * DI + d] = siluf(acc);
}

// ---------------- selective scan: warp per (b,d), lane = state --------------
__global__ void scan_kernel(const float* __restrict__ A_log,
                            const float* __restrict__ Dvec)
{
    const int warp = (blockIdx.x * blockDim.x + threadIdx.x) >> 5;  // 0..4095
    const int lane = threadIdx.x & 31;
    const int b = warp >> 10, d = warp & 1023;

    const float Aa = -expf(A_log[d * DS + lane]);
    const float Dd = Dvec[d];

    float h = 0.0f;
    const int rowbase = b << 10;

    for (int t = 0; t < L_; t++) {
        const int row = rowbase + t;
        float delta = g_DELTA[(size_t)row * DI + d];
        float u     = g_U[(size_t)row * DI + d];
        float Bt    = g_DBC[(size_t)row * DBCW + 32 + lane];
        float Ct    = g_DBC[(size_t)row * DBCW + 64 + lane];

        float dA = expf(delta * Aa);
        h = fmaf(dA, h, (delta * u) * Bt);

        float y = h * Ct;
#pragma unroll
        for (int o = 16; o; o >>= 1) y += __shfl_xor_sync(0xffffffffu, y, o);

        if (lane == 0) {
            float z = g_XZ[(size_t)row * 2048 + 1024 + d];
            g_YACT[(size_t)row * DI + d] = (y + u * Dd) * siluf(z);
        }
    }
}

// ---------------- layernorm over 512 ----------------------------------------
__global__ void ln_kernel(const float* __restrict__ w,
                          const float* __restrict__ bvec)
{
    const int row = blockIdx.x;            // 0..4095
    const int tid = threadIdx.x;           // 256
    const float* y = g_Y2 + (size_t)row * DM;

    float v0 = y[tid], v1 = y[tid + 256];
    float s  = v0 + v1;
    float sq = v0 * v0 + v1 * v1;
#pragma unroll
    for (int o = 16; o; o >>= 1) {
        s  += __shfl_xor_sync(0xffffffffu, s,  o);
        sq += __shfl_xor_sync(0xffffffffu, sq, o);
    }
    __shared__ float ss[8], sqq[8];
    __shared__ float mu_s, rstd_s;
    if ((tid & 31) == 0) { ss[tid >> 5] = s; sqq[tid >> 5] = sq; }
    __syncthreads();
    if (tid == 0) {
        float S = 0.f, SQ = 0.f;
        for (int i = 0; i < 8; i++) { S += ss[i]; SQ += sqq[i]; }
        float mu  = S / 512.0f;
        float var = SQ / 512.0f - mu * mu;
        mu_s = mu;
        rstd_s = rsqrtf(var + 1e-5f);
    }
    __syncthreads();
    float mu = mu_s, r = rstd_s;
    g_YN[(size_t)row * DM + tid]       = (v0 - mu) * r * w[tid]       + bvec[tid];
    g_YN[(size_t)row * DM + tid + 256] = (v1 - mu) * r * w[tid + 256] + bvec[tid + 256];
}

// ---------------- launch ------------------------------------------------------
extern "C" void kernel_launch(void* const* d_in, const int* in_sizes, int n_in,
                              void* d_out, int out_size)
{
    const float* tokens     = (const float*)d_in[0];
    const float* in_proj_w  = (const float*)d_in[1];
    const float* conv_w     = (const float*)d_in[2];
    const float* conv_b     = (const float*)d_in[3];
    const float* x_proj_w   = (const float*)d_in[4];
    const float* dt_proj_w  = (const float*)d_in[5];
    const float* dt_proj_b  = (const float*)d_in[6];
    const float* A_log      = (const float*)d_in[7];
    const float* Dv         = (const float*)d_in[8];
    const float* out_proj_w = (const float*)d_in[9];
    const float* ln_w       = (const float*)d_in[10];
    const float* ln_b       = (const float*)d_in[11];
    const float* lin_w      = (const float*)d_in[12];
    const float* lin_b      = (const float*)d_in[13];
    float* out = (float*)d_out;

    float *XZ, *U, *DBC, *DELTA, *YACT, *Y2, *YN;
    cudaGetSymbolAddress((void**)&XZ,    g_XZ);
    cudaGetSymbolAddress((void**)&U,     g_U);
    cudaGetSymbolAddress((void**)&DBC,   g_DBC);
    cudaGetSymbolAddress((void**)&DELTA, g_DELTA);
    cudaGetSymbolAddress((void**)&YACT,  g_YACT);
    cudaGetSymbolAddress((void**)&Y2,    g_Y2);
    cudaGetSymbolAddress((void**)&YN,    g_YN);

    // 1) xz = perm(tokens) @ in_proj^T      (4096 x 2048, K=512)
    gemm_kernel<0, true><<<dim3(2048 / 128, NROWS / 128), 256>>>(
        tokens, DM, in_proj_w, XZ, 2 * DI, NROWS, 2 * DI, DM, nullptr, nullptr);

    // 2) u = silu(causal depthwise conv(xm) + b)
    conv_silu_kernel<<<NROWS, DI>>>(conv_w, conv_b);

    // 3) dbc = u @ x_proj^T                 (4096 x 96, K=1024)
    gemm_kernel<0, false><<<dim3(1, NROWS / 128), 256>>>(
        U, DI, x_proj_w, DBC, DBCW, NROWS, DBCW, DI, nullptr, nullptr);

    // 4) delta = softplus(dt @ dt_proj^T + b)   (4096 x 1024, K=32)
    gemm_kernel<1, false><<<dim3(1024 / 128, NROWS / 128), 256>>>(
        DBC, DBCW, dt_proj_w, DELTA, DI, NROWS, DI, DR, dt_proj_b, nullptr);

    // 5) selective scan + D skip + silu(z) gate
    scan_kernel<<<1024, 128>>>(A_log, Dv);

    // 6) y2 = yact @ out_proj^T             (4096 x 512, K=1024)
    gemm_kernel<0, false><<<dim3(512 / 128, NROWS / 128), 256>>>(
        YACT, DI, out_proj_w, Y2, DM, NROWS, DM, DI, nullptr, nullptr);

    // 7) layernorm
    ln_kernel<<<NROWS, 256>>>(ln_w, ln_b);

    // 8) out = inv_perm( gelu(yn @ lin^T + b) + residual )  (scatter via perm)
    gemm_kernel<2, false><<<dim3(512 / 128, NROWS / 128), 256>>>(
        YN, DM, lin_w, out, DM, NROWS, DM, DM, lin_b, tokens);
}

// round 3
// speedup vs baseline: 1.4093x; 1.4093x over previous
#include <cuda_runtime.h>
#include <math.h>

#define B_   4
#define L_   1024
#define DM   512
#define DI   1024
#define DS   32
#define DR   32
#define DBCW 96
#define NROWS (B_ * L_)   // 4096

// ---------------- scratch (device globals; no runtime allocation) -----------
__device__ float g_XZ[NROWS * 2 * DI];    // xm = cols [0,1024), z = cols [1024,2048)
__device__ float g_U[NROWS * DI];         // silu(conv(xm))
__device__ float g_DBC[NROWS * DBCW];     // dt | B | C
__device__ float g_DELTA[NROWS * DI];     // softplus(dt @ dt_proj^T + b)
__device__ float g_YACT[NROWS * DI];      // (scan_y + u*D) * silu(z)
__device__ float g_Y2[NROWS * DM];        // yact @ out_proj^T
__device__ float g_YN[NROWS * DM];        // layernorm(y2)

// snake permutation for H=W=32, mode 'tl_row'
__device__ __forceinline__ int permi(int i) {
    int r = i >> 5, c = i & 31;
    int col = (r & 1) ? (31 - c) : c;
    return (r << 5) | col;
}

__device__ __forceinline__ float siluf(float x) {
    return x / (1.0f + __expf(-x));
}
__device__ __forceinline__ float softplusf(float x) {
    return (x > 20.0f) ? x : log1pf(expf(x));
}
__device__ __forceinline__ float geluf(float x) {
    return 0.5f * x * (1.0f + erff(x * 0.70710678118654752f));
}

// ---------------- generic tiled SGEMM: C = A(MxK) * W(NxK)^T -----------------
// Double-buffered smem, 128x128 tile, 8-deep K slab, one sync per slab.
// MODE 0: plain store to C
// MODE 1: softplus(acc + bias[n]) -> C
// MODE 2: gelu(acc + bias[n]) + tokens[permuted row] -> C at permuted row
// PERMA : A row m reads physical row (b*1024 + perm(i))
template<int MODE, bool PERMA>
__global__ __launch_bounds__(256)
void gemm_kernel(const float* __restrict__ A, int lda,
                 const float* __restrict__ W,
                 float* __restrict__ C, int ldc,
                 int M, int N, int K,
                 const float* __restrict__ bias,
                 const float* __restrict__ tokens)
{
    __shared__ float As[2][8][128];
    __shared__ float Bs[2][8][128];

    const int tid = threadIdx.x;           // 256 threads
    const int tx = tid & 15;               // 0..15
    const int ty = tid >> 4;               // 0..15

    const int loadRow = tid >> 1;          // 0..127
    const int loadK   = (tid & 1) * 4;     // 0 or 4

    int m_load = blockIdx.y * 128 + loadRow;
    int arow = m_load;
    if (PERMA) {
        int b = m_load >> 10, i = m_load & 1023;
        arow = (b << 10) + permi(i);
    }
    const float* Aptr = A + (size_t)arow * lda;

    int n_load = blockIdx.x * 128 + loadRow;
    const float* Wptr = W + (size_t)n_load * K;
    const bool wvalid = (n_load < N);

    float acc[8][8];
#pragma unroll
    for (int i = 0; i < 8; i++)
#pragma unroll
        for (int j = 0; j < 8; j++) acc[i][j] = 0.0f;

    // prologue: load slab 0 into buffer 0
    float4 av = *(const float4*)(Aptr + loadK);
    float4 wv = make_float4(0.f, 0.f, 0.f, 0.f);
    if (wvalid) wv = *(const float4*)(Wptr + loadK);
    As[0][loadK + 0][loadRow] = av.x;
    As[0][loadK + 1][loadRow] = av.y;
    As[0][loadK + 2][loadRow] = av.z;
    As[0][loadK + 3][loadRow] = av.w;
    Bs[0][loadK + 0][loadRow] = wv.x;
    Bs[0][loadK + 1][loadRow] = wv.y;
    Bs[0][loadK + 2][loadRow] = wv.z;
    Bs[0][loadK + 3][loadRow] = wv.w;
    __syncthreads();

    int cur = 0;
    for (int kt = 8; kt <= K; kt += 8) {
        // prefetch next slab (if any) into registers early
        if (kt < K) {
            av = *(const float4*)(Aptr + kt + loadK);
            wv = make_float4(0.f, 0.f, 0.f, 0.f);
            if (wvalid) wv = *(const float4*)(Wptr + kt + loadK);
        }

        // compute current slab
#pragma unroll
        for (int kk = 0; kk < 8; kk++) {
            float4 a0 = *(const float4*)&As[cur][kk][ty * 8];
            float4 a1 = *(const float4*)&As[cur][kk][ty * 8 + 4];
            float4 b0 = *(const float4*)&Bs[cur][kk][tx * 8];
            float4 b1 = *(const float4*)&Bs[cur][kk][tx * 8 + 4];
            float ar[8] = {a0.x, a0.y, a0.z, a0.w, a1.x, a1.y, a1.z, a1.w};
            float br[8] = {b0.x, b0.y, b0.z, b0.w, b1.x, b1.y, b1.z, b1.w};
#pragma unroll
            for (int i = 0; i < 8; i++)
#pragma unroll
                for (int j = 0; j < 8; j++)
                    acc[i][j] = fmaf(ar[i], br[j], acc[i][j]);
        }

        if (kt < K) {
            int nxt = cur ^ 1;
            As[nxt][loadK + 0][loadRow] = av.x;
            As[nxt][loadK + 1][loadRow] = av.y;
            As[nxt][loadK + 2][loadRow] = av.z;
            As[nxt][loadK + 3][loadRow] = av.w;
            Bs[nxt][loadK + 0][loadRow] = wv.x;
            Bs[nxt][loadK + 1][loadRow] = wv.y;
            Bs[nxt][loadK + 2][loadRow] = wv.z;
            Bs[nxt][loadK + 3][loadRow] = wv.w;
            __syncthreads();
            cur = nxt;
        }
    }

    const int m0 = blockIdx.y * 128 + ty * 8;
    const int n0 = blockIdx.x * 128 + tx * 8;

#pragma unroll
    for (int i = 0; i < 8; i++) {
        int m = m0 + i;
        if (MODE == 2) {
            int b = m >> 10, ii = m & 1023;
            int row_out = (b << 10) + permi(ii);
#pragma unroll
            for (int j = 0; j < 8; j++) {
                int n = n0 + j;
                if (n < N) {
                    float v = geluf(acc[i][j] + bias[n]);
                    size_t idx = (size_t)row_out * ldc + n;
                    C[idx] = v + tokens[idx];
                }
            }
        } else {
#pragma unroll
            for (int j = 0; j < 8; j++) {
                int n = n0 + j;
                if (n < N) {
                    float v = acc[i][j];
                    if (MODE == 1) v = softplusf(v + bias[n]);
                    C[(size_t)m * ldc + n] = v;
                }
            }
        }
    }
}

// ---------------- depthwise causal conv (k=4, left pad 3) + bias + silu ------
__global__ void conv_silu_kernel(const float* __restrict__ conv_w,
                                 const float* __restrict__ conv_b)
{
    const int d  = threadIdx.x;            // 0..1023
    const int bt = blockIdx.x;             // 0..4095
    const int b = bt >> 10, t = bt & 1023;

    float w0 = conv_w[d * 4 + 0];
    float w1 = conv_w[d * 4 + 1];
    float w2 = conv_w[d * 4 + 2];
    float w3 = conv_w[d * 4 + 3];

    const size_t base = ((size_t)(b << 10)) * 2048 + d;
    float acc = conv_b[d];
    if (t - 3 >= 0) acc = fmaf(w0, g_XZ[base + (size_t)(t - 3) * 2048], acc);
    if (t - 2 >= 0) acc = fmaf(w1, g_XZ[base + (size_t)(t - 2) * 2048], acc);
    if (t - 1 >= 0) acc = fmaf(w2, g_XZ[base + (size_t)(t - 1) * 2048], acc);
    acc = fmaf(w3, g_XZ[base + (size_t)t * 2048], acc);

    g_U[(size_t)bt * DI + d] = siluf(acc);
}

// ---------------- selective scan: warp per (b,d), lane = state --------------
// 32-step groups: fully unrolled so the 128 independent LDGs per group are
// front-batched (high MLP); per-step epilogue removed — each lane banks the
// y of "its" step, one gated store per 32 steps.
__global__ void scan_kernel(const float* __restrict__ A_log,
                            const float* __restrict__ Dvec)
{
    const int warp = (blockIdx.x * blockDim.x + threadIdx.x) >> 5;  // 0..4095
    const int lane = threadIdx.x & 31;
    const int b = warp >> 10, d = warp & 1023;

    const float Aa = -__expf(A_log[d * DS + lane]);
    const float Dd = Dvec[d];

    float h = 0.0f;
    const int rowbase = b << 10;

    const float* pD = g_DELTA + (size_t)rowbase * DI + d;
    const float* pU = g_U     + (size_t)rowbase * DI + d;
    const float* pB = g_DBC   + (size_t)rowbase * DBCW + 32 + lane;
    const float* pC = pB + 32;

    for (int t0 = 0; t0 < L_; t0 += 32) {
        float yout = 0.0f;
#pragma unroll
        for (int s = 0; s < 32; s++) {
            const int t = t0 + s;
            float delta = __ldg(pD + (size_t)t * DI);
            float u     = __ldg(pU + (size_t)t * DI);
            float Bt    = __ldg(pB + (size_t)t * DBCW);
            float Ct    = __ldg(pC + (size_t)t * DBCW);

            float dA = __expf(delta * Aa);
            h = fmaf(dA, h, (delta * u) * Bt);

            float y = h * Ct;
#pragma unroll
            for (int o = 16; o; o >>= 1) y += __shfl_xor_sync(0xffffffffu, y, o);
            y = fmaf(u, Dd, y);
            if (lane == s) yout = y;
        }
        // epilogue: lane holds y for step t0+lane
        const int row = rowbase + t0 + lane;
        float z = g_XZ[(size_t)row * 2048 + 1024 + d];
        g_YACT[(size_t)row * DI + d] = yout * siluf(z);
    }
}

// ---------------- layernorm over 512 ----------------------------------------
__global__ void ln_kernel(const float* __restrict__ w,
                          const float* __restrict__ bvec)
{
    const int row = blockIdx.x;            // 0..4095
    const int tid = threadIdx.x;           // 256
    const float* y = g_Y2 + (size_t)row * DM;

    float v0 = y[tid], v1 = y[tid + 256];
    float s  = v0 + v1;
    float sq = v0 * v0 + v1 * v1;
#pragma unroll
    for (int o = 16; o; o >>= 1) {
        s  += __shfl_xor_sync(0xffffffffu, s,  o);
        sq += __shfl_xor_sync(0xffffffffu, sq, o);
    }
    __shared__ float ss[8], sqq[8];
    __shared__ float mu_s, rstd_s;
    if ((tid & 31) == 0) { ss[tid >> 5] = s; sqq[tid >> 5] = sq; }
    __syncthreads();
    if (tid == 0) {
        float S = 0.f, SQ = 0.f;
        for (int i = 0; i < 8; i++) { S += ss[i]; SQ += sqq[i]; }
        float mu  = S / 512.0f;
        float var = SQ / 512.0f - mu * mu;
        mu_s = mu;
        rstd_s = rsqrtf(var + 1e-5f);
    }
    __syncthreads();
    float mu = mu_s, r = rstd_s;
    g_YN[(size_t)row * DM + tid]       = (v0 - mu) * r * w[tid]       + bvec[tid];
    g_YN[(size_t)row * DM + tid + 256] = (v1 - mu) * r * w[tid + 256] + bvec[tid + 256];
}

// ---------------- launch ------------------------------------------------------
extern "C" void kernel_launch(void* const* d_in, const int* in_sizes, int n_in,
                              void* d_out, int out_size)
{
    const float* tokens     = (const float*)d_in[0];
    const float* in_proj_w  = (const float*)d_in[1];
    const float* conv_w     = (const float*)d_in[2];
    const float* conv_b     = (const float*)d_in[3];
    const float* x_proj_w   = (const float*)d_in[4];
    const float* dt_proj_w  = (const float*)d_in[5];
    const float* dt_proj_b  = (const float*)d_in[6];
    const float* A_log      = (const float*)d_in[7];
    const float* Dv         = (const float*)d_in[8];
    const float* out_proj_w = (const float*)d_in[9];
    const float* ln_w       = (const float*)d_in[10];
    const float* ln_b       = (const float*)d_in[11];
    const float* lin_w      = (const float*)d_in[12];
    const float* lin_b      = (const float*)d_in[13];
    float* out = (float*)d_out;

    float *XZ, *U, *DBC, *DELTA, *YACT, *Y2, *YN;
    cudaGetSymbolAddress((void**)&XZ,    g_XZ);
    cudaGetSymbolAddress((void**)&U,     g_U);
    cudaGetSymbolAddress((void**)&DBC,   g_DBC);
    cudaGetSymbolAddress((void**)&DELTA, g_DELTA);
    cudaGetSymbolAddress((void**)&YACT,  g_YACT);
    cudaGetSymbolAddress((void**)&Y2,    g_Y2);
    cudaGetSymbolAddress((void**)&YN,    g_YN);

    // 1) xz = perm(tokens) @ in_proj^T      (4096 x 2048, K=512)
    gemm_kernel<0, true><<<dim3(2048 / 128, NROWS / 128), 256>>>(
        tokens, DM, in_proj_w, XZ, 2 * DI, NROWS, 2 * DI, DM, nullptr, nullptr);

    // 2) u = silu(causal depthwise conv(xm) + b)
    conv_silu_kernel<<<NROWS, DI>>>(conv_w, conv_b);

    // 3) dbc = u @ x_proj^T                 (4096 x 96, K=1024)
    gemm_kernel<0, false><<<dim3(1, NROWS / 128), 256>>>(
        U, DI, x_proj_w, DBC, DBCW, NROWS, DBCW, DI, nullptr, nullptr);

    // 4) delta = softplus(dt @ dt_proj^T + b)   (4096 x 1024, K=32)
    gemm_kernel<1, false><<<dim3(1024 / 128, NROWS / 128), 256>>>(
        DBC, DBCW, dt_proj_w, DELTA, DI, NROWS, DI, DR, dt_proj_b, nullptr);

    // 5) selective scan + D skip + silu(z) gate
    scan_kernel<<<1024, 128>>>(A_log, Dv);

    // 6) y2 = yact @ out_proj^T             (4096 x 512, K=1024)
    gemm_kernel<0, false><<<dim3(512 / 128, NROWS / 128), 256>>>(
        YACT, DI, out_proj_w, Y2, DM, NROWS, DM, DI, nullptr, nullptr);

    // 7) layernorm
    ln_kernel<<<NROWS, 256>>>(ln_w, ln_b);

    // 8) out = inv_perm( gelu(yn @ lin^T + b) + residual )
    gemm_kernel<2, false><<<dim3(512 / 128, NROWS / 128), 256>>>(
        YN, DM, lin_w, out, DM, NROWS, DM, DM, lin_b, tokens);
}

// round 5
// speedup vs baseline: 2.1696x; 1.5394x over previous
#include <cuda_runtime.h>
#include <cuda_bf16.h>
#include <cstdint>
#include <math.h>

#define B_   4
#define L_   1024
#define DM   512
#define DI   1024
#define DS   32
#define DR   32
#define DBCW 96
#define NROWS (B_ * L_)   // 4096

// tensor GEMM tiling
#define BM 128
#define BN 128
#define BK 16
#define LDSROW 24   // bf16 elements per smem row (48 bytes, conflict-free ldmatrix)

// ---------------- scratch (device globals; no runtime allocation) -----------
__device__ float g_XZ[NROWS * 2 * DI];    // xm = cols [0,1024), z = cols [1024,2048)
__device__ float g_U[NROWS * DI];         // silu(conv(xm))
__device__ float g_DBC[NROWS * DBCW];     // dt | B | C
__device__ float g_DELTA[NROWS * DI];     // softplus(dt @ dt_proj^T + b)
__device__ float g_YACT[NROWS * DI];      // (scan_y + u*D) * silu(z)
__device__ float g_Y2[NROWS * DM];        // yact @ out_proj^T
__device__ float g_YN[NROWS * DM];        // layernorm(y2)

// snake permutation for H=W=32, mode 'tl_row'
__device__ __forceinline__ int permi(int i) {
    int r = i >> 5, c = i & 31;
    int col = (r & 1) ? (31 - c) : c;
    return (r << 5) | col;
}

__device__ __forceinline__ float siluf(float x) {
    return x / (1.0f + __expf(-x));
}
__device__ __forceinline__ float softplusf(float x) {
    return (x > 20.0f) ? x : log1pf(expf(x));
}
__device__ __forceinline__ float geluf(float x) {
    return 0.5f * x * (1.0f + erff(x * 0.70710678118654752f));
}

// split fp32 float4 into bf16 hi + lo (packed 2x u32 each)
__device__ __forceinline__ void cvt_hilo(float4 v, uint2& hw, uint2& lw) {
    __nv_bfloat16 h0 = __float2bfloat16(v.x);
    __nv_bfloat16 h1 = __float2bfloat16(v.y);
    __nv_bfloat16 h2 = __float2bfloat16(v.z);
    __nv_bfloat16 h3 = __float2bfloat16(v.w);
    __nv_bfloat16 l0 = __float2bfloat16(v.x - __bfloat162float(h0));
    __nv_bfloat16 l1 = __float2bfloat16(v.y - __bfloat162float(h1));
    __nv_bfloat16 l2 = __float2bfloat16(v.z - __bfloat162float(h2));
    __nv_bfloat16 l3 = __float2bfloat16(v.w - __bfloat162float(h3));
    hw.x = (uint32_t)__bfloat16_as_ushort(h0) | ((uint32_t)__bfloat16_as_ushort(h1) << 16);
    hw.y = (uint32_t)__bfloat16_as_ushort(h2) | ((uint32_t)__bfloat16_as_ushort(h3) << 16);
    lw.x = (uint32_t)__bfloat16_as_ushort(l0) | ((uint32_t)__bfloat16_as_ushort(l1) << 16);
    lw.y = (uint32_t)__bfloat16_as_ushort(l2) | ((uint32_t)__bfloat16_as_ushort(l3) << 16);
}

__device__ __forceinline__ void ldsm_x4(uint32_t* d, uint32_t saddr) {
    asm volatile("ldmatrix.sync.aligned.m8n8.x4.shared.b16 {%0,%1,%2,%3}, [%4];"
                 : "=r"(d[0]), "=r"(d[1]), "=r"(d[2]), "=r"(d[3]) : "r"(saddr));
}

__device__ __forceinline__ void mma_bf16(float* c, const uint32_t* a, const uint32_t* b) {
    asm volatile("mma.sync.aligned.m16n8k16.row.col.f32.bf16.bf16.f32 "
                 "{%0,%1,%2,%3}, {%4,%5,%6,%7}, {%8,%9}, {%0,%1,%2,%3};"
                 : "+f"(c[0]), "+f"(c[1]), "+f"(c[2]), "+f"(c[3])
                 : "r"(a[0]), "r"(a[1]), "r"(a[2]), "r"(a[3]), "r"(b[0]), "r"(b[1]));
}

// ---------------- tensor-core GEMM: C = A(MxK) * W(NxK)^T, bf16x3 -----------
// MODE 0: plain store       MODE 1: softplus(acc+bias)     MODE 2: gelu(acc+bias)+tokens, row-permuted scatter
// PERMA : A row m reads physical row (b*1024 + perm(i))
template<int MODE, bool PERMA>
__global__ __launch_bounds__(256, 1)
void tgemm(const float* __restrict__ A, int lda,
           const float* __restrict__ W,
           float* __restrict__ C, int ldc,
           int M, int N, int K,
           const float* __restrict__ bias,
           const float* __restrict__ tokens)
{
    __shared__ __align__(16) __nv_bfloat16 sAh[2][BM * LDSROW];
    __shared__ __align__(16) __nv_bfloat16 sAl[2][BM * LDSROW];
    __shared__ __align__(16) __nv_bfloat16 sBh[2][BN * LDSROW];
    __shared__ __align__(16) __nv_bfloat16 sBl[2][BN * LDSROW];

    const int tid  = threadIdx.x;
    const int lane = tid & 31;
    const int wid  = tid >> 5;
    const int wm   = wid >> 2;   // 0..1  (m warp row, 64 rows each)
    const int wn   = wid & 3;    // 0..3  (n warp col, 32 cols each)

    // ---- loader: 2 tasks/thread, each one float4 of a row ----
    const int t1  = tid + 256;
    const int ar0 = tid >> 2, ak0 = (tid & 3) << 2;
    const int ar1 = t1  >> 2, ak1 = (t1  & 3) << 2;

    const int am0 = blockIdx.y * BM + ar0;
    const int am1 = blockIdx.y * BM + ar1;
    int arow0 = am0, arow1 = am1;
    if (PERMA) {
        arow0 = (am0 & ~1023) + permi(am0 & 1023);
        arow1 = (am1 & ~1023) + permi(am1 & 1023);
    }
    const float* pA0 = A + (size_t)arow0 * lda + ak0;
    const float* pA1 = A + (size_t)arow1 * lda + ak1;

    const int nr0 = blockIdx.x * BN + ar0;
    const int nr1 = blockIdx.x * BN + ar1;
    const bool bv0 = nr0 < N, bv1 = nr1 < N;
    const float* pB0 = W + (size_t)(bv0 ? nr0 : 0) * K + ak0;
    const float* pB1 = W + (size_t)(bv1 ? nr1 : 0) * K + ak1;

    const int so0 = ar0 * LDSROW + ak0;
    const int so1 = ar1 * LDSROW + ak1;

    // ---- ldmatrix lane offsets (element units) ----
    const int q = lane >> 3, rr8 = lane & 7;
    const int aoff = (rr8 + ((q & 1) << 3)) * LDSROW + ((q >> 1) << 3);

    float acc[4][4][4];
#pragma unroll
    for (int i = 0; i < 4; i++)
#pragma unroll
        for (int j = 0; j < 4; j++)
#pragma unroll
            for (int k = 0; k < 4; k++) acc[i][j][k] = 0.0f;

    const int nslab = K / BK;

    // prologue: slab 0
    float4 fa0 = *(const float4*)pA0;
    float4 fa1 = *(const float4*)pA1;
    float4 fb0 = bv0 ? *(const float4*)pB0 : make_float4(0.f,0.f,0.f,0.f);
    float4 fb1 = bv1 ? *(const float4*)pB1 : make_float4(0.f,0.f,0.f,0.f);
    {
        uint2 hw, lw;
        cvt_hilo(fa0, hw, lw); *(uint2*)&sAh[0][so0] = hw; *(uint2*)&sAl[0][so0] = lw;
        cvt_hilo(fa1, hw, lw); *(uint2*)&sAh[0][so1] = hw; *(uint2*)&sAl[0][so1] = lw;
        cvt_hilo(fb0, hw, lw); *(uint2*)&sBh[0][so0] = hw; *(uint2*)&sBl[0][so0] = lw;
        cvt_hilo(fb1, hw, lw); *(uint2*)&sBh[0][so1] = hw; *(uint2*)&sBl[0][so1] = lw;
    }
    __syncthreads();

    for (int s = 0; s < nslab; s++) {
        const int buf = s & 1;
        const bool more = (s + 1 < nslab);
        if (more) {
            const int off = (s + 1) * BK;
            fa0 = *(const float4*)(pA0 + off);
            fa1 = *(const float4*)(pA1 + off);
            fb0 = bv0 ? *(const float4*)(pB0 + off) : make_float4(0.f,0.f,0.f,0.f);
            fb1 = bv1 ? *(const float4*)(pB1 + off) : make_float4(0.f,0.f,0.f,0.f);
        }

        // ---- ldmatrix loads ----
        uint32_t ah[4][4], al[4][4], bh[4][2], bl[4][2];
        const uint32_t bAh = (uint32_t)__cvta_generic_to_shared(&sAh[buf][0]);
        const uint32_t bAl = (uint32_t)__cvta_generic_to_shared(&sAl[buf][0]);
        const uint32_t bBh = (uint32_t)__cvta_generic_to_shared(&sBh[buf][0]);
        const uint32_t bBl = (uint32_t)__cvta_generic_to_shared(&sBl[buf][0]);
#pragma unroll
        for (int mi = 0; mi < 4; mi++) {
            const uint32_t eo = (uint32_t)(((wm * 64 + mi * 16) * LDSROW + aoff) * 2);
            ldsm_x4(ah[mi], bAh + eo);
            ldsm_x4(al[mi], bAl + eo);
        }
        // B: x4 returns {b0(n0-7), b0(n8-15), b1(n0-7), b1(n8-15)} — demux pairs
#pragma unroll
        for (int pn = 0; pn < 2; pn++) {
            const uint32_t eo = (uint32_t)(((wn * 32 + pn * 16) * LDSROW + aoff) * 2);
            uint32_t t[4];
            ldsm_x4(t, bBh + eo);
            bh[pn * 2][0]     = t[0]; bh[pn * 2][1]     = t[2];
            bh[pn * 2 + 1][0] = t[1]; bh[pn * 2 + 1][1] = t[3];
            ldsm_x4(t, bBl + eo);
            bl[pn * 2][0]     = t[0]; bl[pn * 2][1]     = t[2];
            bl[pn * 2 + 1][0] = t[1]; bl[pn * 2 + 1][1] = t[3];
        }

        // ---- mma: hi*hi + hi*lo + lo*hi ----
#pragma unroll
        for (int mi = 0; mi < 4; mi++)
#pragma unroll
            for (int ni = 0; ni < 4; ni++) {
                mma_bf16(acc[mi][ni], ah[mi], bh[ni]);
                mma_bf16(acc[mi][ni], ah[mi], bl[ni]);
                mma_bf16(acc[mi][ni], al[mi], bh[ni]);
            }

        if (more) {
            const int nb = buf ^ 1;
            uint2 hw, lw;
            cvt_hilo(fa0, hw, lw); *(uint2*)&sAh[nb][so0] = hw; *(uint2*)&sAl[nb][so0] = lw;
            cvt_hilo(fa1, hw, lw); *(uint2*)&sAh[nb][so1] = hw; *(uint2*)&sAl[nb][so1] = lw;
            cvt_hilo(fb0, hw, lw); *(uint2*)&sBh[nb][so0] = hw; *(uint2*)&sBl[nb][so0] = lw;
            cvt_hilo(fb1, hw, lw); *(uint2*)&sBh[nb][so1] = hw; *(uint2*)&sBl[nb][so1] = lw;
            __syncthreads();
        }
    }

    // ---- epilogue ----
    const int g  = lane >> 2;
    const int tc = (lane & 3) << 1;
#pragma unroll
    for (int mi = 0; mi < 4; mi++) {
        const int mA = blockIdx.y * BM + wm * 64 + mi * 16 + g;
        const int mB = mA + 8;
        int rowA = mA, rowB = mB;
        if (MODE == 2) {
            rowA = (mA & ~1023) + permi(mA & 1023);
            rowB = (mB & ~1023) + permi(mB & 1023);
        }
#pragma unroll
        for (int ni = 0; ni < 4; ni++) {
            const int n0 = blockIdx.x * BN + wn * 32 + ni * 8 + tc;
            if (n0 < N) {
                float v0 = acc[mi][ni][0], v1 = acc[mi][ni][1];
                float v2 = acc[mi][ni][2], v3 = acc[mi][ni][3];
                if (MODE == 1) {
                    float2 bb = *(const float2*)&bias[n0];
                    v0 = softplusf(v0 + bb.x); v1 = softplusf(v1 + bb.y);
                    v2 = softplusf(v2 + bb.x); v3 = softplusf(v3 + bb.y);
                }
                if (MODE == 2) {
                    float2 bb = *(const float2*)&bias[n0];
                    float2 r0 = *(const float2*)&tokens[(size_t)rowA * ldc + n0];
                    float2 r1 = *(const float2*)&tokens[(size_t)rowB * ldc + n0];
                    v0 = geluf(v0 + bb.x) + r0.x; v1 = geluf(v1 + bb.y) + r0.y;
                    v2 = geluf(v2 + bb.x) + r1.x; v3 = geluf(v3 + bb.y) + r1.y;
                }
                *(float2*)&C[(size_t)rowA * ldc + n0] = make_float2(v0, v1);
                *(float2*)&C[(size_t)rowB * ldc + n0] = make_float2(v2, v3);
            }
        }
    }
}

// ---------------- depthwise causal conv (k=4, left pad 3) + bias + silu ------
__global__ void conv_silu_kernel(const float* __restrict__ conv_w,
                                 const float* __restrict__ conv_b)
{
    const int d  = threadIdx.x;            // 0..1023
    const int bt = blockIdx.x;             // 0..4095
    const int b = bt >> 10, t = bt & 1023;

    float w0 = conv_w[d * 4 + 0];
    float w1 = conv_w[d * 4 + 1];
    float w2 = conv_w[d * 4 + 2];
    float w3 = conv_w[d * 4 + 3];

    const size_t base = ((size_t)(b << 10)) * 2048 + d;
    float acc = conv_b[d];
    if (t - 3 >= 0) acc = fmaf(w0, g_XZ[base + (size_t)(t - 3) * 2048], acc);
    if (t - 2 >= 0) acc = fmaf(w1, g_XZ[base + (size_t)(t - 2) * 2048], acc);
    if (t - 1 >= 0) acc = fmaf(w2, g_XZ[base + (size_t)(t - 1) * 2048], acc);
    acc = fmaf(w3, g_XZ[base + (size_t)t * 2048], acc);

    g_U[(size_t)bt * DI + d] = siluf(acc);
}

// ---------------- selective scan: warp per (b,d), lane = state --------------
__global__ void scan_kernel(const float* __restrict__ A_log,
                            const float* __restrict__ Dvec)
{
    const int warp = (blockIdx.x * blockDim.x + threadIdx.x) >> 5;  // 0..4095
    const int lane = threadIdx.x & 31;
    const int b = warp >> 10, d = warp & 1023;

    const float Aa = -__expf(A_log[d * DS + lane]);
    const float Dd = Dvec[d];

    float h = 0.0f;
    const int rowbase = b << 10;

    const float* pD = g_DELTA + (size_t)rowbase * DI + d;
    const float* pU = g_U     + (size_t)rowbase * DI + d;
    const float* pB = g_DBC   + (size_t)rowbase * DBCW + 32 + lane;
    const float* pC = pB + 32;

    for (int t0 = 0; t0 < L_; t0 += 32) {
        float yout = 0.0f;
#pragma unroll
        for (int s = 0; s < 32; s++) {
            const int t = t0 + s;
            float delta = __ldg(pD + (size_t)t * DI);
            float u     = __ldg(pU + (size_t)t * DI);
            float Bt    = __ldg(pB + (size_t)t * DBCW);
            float Ct    = __ldg(pC + (size_t)t * DBCW);

            float dA = __expf(delta * Aa);
            h = fmaf(dA, h, (delta * u) * Bt);

            float y = h * Ct;
#pragma unroll
            for (int o = 16; o; o >>= 1) y += __shfl_xor_sync(0xffffffffu, y, o);
            y = fmaf(u, Dd, y);
            if (lane == s) yout = y;
        }
        const int row = rowbase + t0 + lane;
        float z = g_XZ[(size_t)row * 2048 + 1024 + d];
        g_YACT[(size_t)row * DI + d] = yout * siluf(z);
    }
}

// ---------------- layernorm over 512 ----------------------------------------
__global__ void ln_kernel(const float* __restrict__ w,
                          const float* __restrict__ bvec)
{
    const int row = blockIdx.x;            // 0..4095
    const int tid = threadIdx.x;           // 256
    const float* y = g_Y2 + (size_t)row * DM;

    float v0 = y[tid], v1 = y[tid + 256];
    float s  = v0 + v1;
    float sq = v0 * v0 + v1 * v1;
#pragma unroll
    for (int o = 16; o; o >>= 1) {
        s  += __shfl_xor_sync(0xffffffffu, s,  o);
        sq += __shfl_xor_sync(0xffffffffu, sq, o);
    }
    __shared__ float ss[8], sqq[8];
    __shared__ float mu_s, rstd_s;
    if ((tid & 31) == 0) { ss[tid >> 5] = s; sqq[tid >> 5] = sq; }
    __syncthreads();
    if (tid == 0) {
        float S = 0.f, SQ = 0.f;
        for (int i = 0; i < 8; i++) { S += ss[i]; SQ += sqq[i]; }
        float mu  = S / 512.0f;
        float var = SQ / 512.0f - mu * mu;
        mu_s = mu;
        rstd_s = rsqrtf(var + 1e-5f);
    }
    __syncthreads();
    float mu = mu_s, rv = rstd_s;
    g_YN[(size_t)row * DM + tid]       = (v0 - mu) * rv * w[tid]       + bvec[tid];
    g_YN[(size_t)row * DM + tid + 256] = (v1 - mu) * rv * w[tid + 256] + bvec[tid + 256];
}

// ---------------- launch ------------------------------------------------------
extern "C" void kernel_launch(void* const* d_in, const int* in_sizes, int n_in,
                              void* d_out, int out_size)
{
    const float* tokens     = (const float*)d_in[0];
    const float* in_proj_w  = (const float*)d_in[1];
    const float* conv_w     = (const float*)d_in[2];
    const float* conv_b     = (const float*)d_in[3];
    const float* x_proj_w   = (const float*)d_in[4];
    const float* dt_proj_w  = (const float*)d_in[5];
    const float* dt_proj_b  = (const float*)d_in[6];
    const float* A_log      = (const float*)d_in[7];
    const float* Dv         = (const float*)d_in[8];
    const float* out_proj_w = (const float*)d_in[9];
    const float* ln_w       = (const float*)d_in[10];
    const float* ln_b       = (const float*)d_in[11];
    const float* lin_w      = (const float*)d_in[12];
    const float* lin_b      = (const float*)d_in[13];
    float* out = (float*)d_out;

    float *XZ, *U, *DBC, *DELTA, *YACT, *Y2, *YN;
    cudaGetSymbolAddress((void**)&XZ,    g_XZ);
    cudaGetSymbolAddress((void**)&U,     g_U);
    cudaGetSymbolAddress((void**)&DBC,   g_DBC);
    cudaGetSymbolAddress((void**)&DELTA, g_DELTA);
    cudaGetSymbolAddress((void**)&YACT,  g_YACT);
    cudaGetSymbolAddress((void**)&Y2,    g_Y2);
    cudaGetSymbolAddress((void**)&YN,    g_YN);

    // 1) xz = perm(tokens) @ in_proj^T      (4096 x 2048, K=512)
    tgemm<0, true><<<dim3(2048 / BN, NROWS / BM), 256>>>(
        tokens, DM, in_proj_w, XZ, 2 * DI, NROWS, 2 * DI, DM, nullptr, nullptr);

    // 2) u = silu(causal depthwise conv(xm) + b)
    conv_silu_kernel<<<NROWS, DI>>>(conv_w, conv_b);

    // 3) dbc = u @ x_proj^T                 (4096 x 96, K=1024)
    tgemm<0, false><<<dim3(1, NROWS / BM), 256>>>(
        U, DI, x_proj_w, DBC, DBCW, NROWS, DBCW, DI, nullptr, nullptr);

    // 4) delta = softplus(dt @ dt_proj^T + b)   (4096 x 1024, K=32)
    tgemm<1, false><<<dim3(1024 / BN, NROWS / BM), 256>>>(
        DBC, DBCW, dt_proj_w, DELTA, DI, NROWS, DI, DR, dt_proj_b, nullptr);

    // 5) selective scan + D skip + silu(z) gate
    scan_kernel<<<1024, 128>>>(A_log, Dv);

    // 6) y2 = yact @ out_proj^T             (4096 x 512, K=1024)
    tgemm<0, false><<<dim3(512 / BN, NROWS / BM), 256>>>(
        YACT, DI, out_proj_w, Y2, DM, NROWS, DM, DI, nullptr, nullptr);

    // 7) layernorm
    ln_kernel<<<NROWS, 256>>>(ln_w, ln_b);

    // 8) out = inv_perm( gelu(yn @ lin^T + b) + residual )
    tgemm<2, false><<<dim3(512 / BN, NROWS / BM), 256>>>(
        YN, DM, lin_w, out, DM, NROWS, DM, DM, lin_b, tokens);
}

// round 6
// speedup vs baseline: 2.6108x; 1.2033x over previous
#include <cuda_runtime.h>
#include <cuda_bf16.h>
#include <cstdint>
#include <math.h>

#define B_   4
#define L_   1024
#define DM   512
#define DI   1024
#define DS   32
#define DR   32
#define DBCW 96
#define NROWS (B_ * L_)   // 4096

// tensor GEMM tiling
#define BM 128
#define BN 128
#define BK 16
#define LDSROW 24   // bf16 elements per smem row (48 bytes, conflict-free ldmatrix)

// ---------------- fp32 scratch -----------------------------------------------
__device__ float g_XZ[NROWS * 2 * DI];    // xm | z
__device__ float g_U[NROWS * DI];         // silu(conv(xm))  (scan input)
__device__ float g_DBC[NROWS * DBCW];     // dt | B | C       (scan input)
__device__ float g_DELTA[NROWS * DI];     // softplus(...)    (scan input)
__device__ float g_Y2[NROWS * DM];        // out_proj output  (ln input)

// ---------------- bf16 hi/lo planes ------------------------------------------
__device__ __align__(16) __nv_bfloat16 g_TOKh[NROWS * DM],  g_TOKl[NROWS * DM];
__device__ __align__(16) __nv_bfloat16 g_W1h[2048 * DM],    g_W1l[2048 * DM];
__device__ __align__(16) __nv_bfloat16 g_W2h[DBCW * DI],    g_W2l[DBCW * DI];
__device__ __align__(16) __nv_bfloat16 g_W3h[DI * DR],      g_W3l[DI * DR];
__device__ __align__(16) __nv_bfloat16 g_W4h[DM * DI],      g_W4l[DM * DI];
__device__ __align__(16) __nv_bfloat16 g_W5h[DM * DM],      g_W5l[DM * DM];
__device__ __align__(16) __nv_bfloat16 g_Uh[NROWS * DI],    g_Ul[NROWS * DI];
__device__ __align__(16) __nv_bfloat16 g_DBCh[NROWS * DBCW],g_DBCl[NROWS * DBCW];
__device__ __align__(16) __nv_bfloat16 g_YAh[NROWS * DI],   g_YAl[NROWS * DI];
__device__ __align__(16) __nv_bfloat16 g_YNh[NROWS * DM],   g_YNl[NROWS * DM];

// snake permutation for H=W=32, mode 'tl_row'
__device__ __forceinline__ int permi(int i) {
    int r = i >> 5, c = i & 31;
    int col = (r & 1) ? (31 - c) : c;
    return (r << 5) | col;
}

__device__ __forceinline__ float siluf(float x) { return x / (1.0f + __expf(-x)); }
__device__ __forceinline__ float softplusf(float x) {
    return (x > 20.0f) ? x : log1pf(expf(x));
}
__device__ __forceinline__ float geluf(float x) {
    return 0.5f * x * (1.0f + erff(x * 0.70710678118654752f));
}

__device__ __forceinline__ void split_bf(float v, __nv_bfloat16& h, __nv_bfloat16& l) {
    h = __float2bfloat16(v);
    l = __float2bfloat16(v - __bfloat162float(h));
}
__device__ __forceinline__ uint32_t pack2(__nv_bfloat16 a, __nv_bfloat16 b) {
    return (uint32_t)__bfloat16_as_ushort(a) | ((uint32_t)__bfloat16_as_ushort(b) << 16);
}
__device__ __forceinline__ void cvt_hilo(float4 v, uint2& hw, uint2& lw) {
    __nv_bfloat16 h0, h1, h2, h3, l0, l1, l2, l3;
    split_bf(v.x, h0, l0); split_bf(v.y, h1, l1);
    split_bf(v.z, h2, l2); split_bf(v.w, h3, l3);
    hw.x = pack2(h0, h1); hw.y = pack2(h2, h3);
    lw.x = pack2(l0, l1); lw.y = pack2(l2, l3);
}

// elementwise fp32 -> (hi, lo) bf16 planes
__global__ void cvt_kernel(const float4* __restrict__ src,
                           uint2* __restrict__ h, uint2* __restrict__ l, int n4)
{
    int i = blockIdx.x * blockDim.x + threadIdx.x;
    if (i < n4) {
        uint2 hw, lw;
        cvt_hilo(src[i], hw, lw);
        h[i] = hw; l[i] = lw;
    }
}

__device__ __forceinline__ void ldsm_x4(uint32_t* d, uint32_t saddr) {
    asm volatile("ldmatrix.sync.aligned.m8n8.x4.shared.b16 {%0,%1,%2,%3}, [%4];"
                 : "=r"(d[0]), "=r"(d[1]), "=r"(d[2]), "=r"(d[3]) : "r"(saddr));
}

__device__ __forceinline__ void mma_bf16(float* c, const uint32_t* a, const uint32_t* b) {
    asm volatile("mma.sync.aligned.m16n8k16.row.col.f32.bf16.bf16.f32 "
                 "{%0,%1,%2,%3}, {%4,%5,%6,%7}, {%8,%9}, {%0,%1,%2,%3};"
                 : "+f"(c[0]), "+f"(c[1]), "+f"(c[2]), "+f"(c[3])
                 : "r"(a[0]), "r"(a[1]), "r"(a[2]), "r"(a[3]), "r"(b[0]), "r"(b[1]));
}

// ---------------- tensor-core GEMM: C = A(MxK) * W(NxK)^T, bf16x3 ------------
// Inputs are pre-split bf16 hi/lo planes. No conversion in the hot loop.
// MODE 0: plain fp32 store   MODE 1: softplus(acc+bias)   MODE 2: gelu(acc+bias)+tokens, permuted scatter
// PERMA : A row m reads physical row (b*1024 + perm(i))
// BFOUT : additionally emit bf16 hi/lo planes of the output (same ldc)
template<int MODE, bool PERMA, bool BFOUT>
__global__ __launch_bounds__(256, 1)
void tgemm(const __nv_bfloat16* __restrict__ Ah, const __nv_bfloat16* __restrict__ Al, int lda,
           const __nv_bfloat16* __restrict__ Wh, const __nv_bfloat16* __restrict__ Wl,
           float* __restrict__ C, int ldc,
           int M, int N, int K,
           const float* __restrict__ bias,
           const float* __restrict__ tokens,
           __nv_bfloat16* __restrict__ Ch, __nv_bfloat16* __restrict__ Cl)
{
    __shared__ __align__(16) __nv_bfloat16 sAh[2][BM * LDSROW];
    __shared__ __align__(16) __nv_bfloat16 sAl[2][BM * LDSROW];
    __shared__ __align__(16) __nv_bfloat16 sBh[2][BN * LDSROW];
    __shared__ __align__(16) __nv_bfloat16 sBl[2][BN * LDSROW];

    const int tid  = threadIdx.x;
    const int lane = tid & 31;
    const int wid  = tid >> 5;
    const int wm   = wid >> 2;   // 0..1
    const int wn   = wid & 3;    // 0..3

    // ---- loader: thread -> (row = tid>>1, k-offset = (tid&1)*8), one uint4 per plane
    const int lr = tid >> 1;           // 0..127
    const int lk = (tid & 1) << 3;     // 0 or 8

    const int am = blockIdx.y * BM + lr;
    int arow = am;
    if (PERMA) arow = (am & ~1023) + permi(am & 1023);
    const __nv_bfloat16* pAh = Ah + (size_t)arow * lda + lk;
    const __nv_bfloat16* pAl = Al + (size_t)arow * lda + lk;

    const int nr = blockIdx.x * BN + lr;
    const bool bv = nr < N;
    const __nv_bfloat16* pWh = Wh + (size_t)(bv ? nr : 0) * K + lk;
    const __nv_bfloat16* pWl = Wl + (size_t)(bv ? nr : 0) * K + lk;

    const int so = lr * LDSROW + lk;

    // ---- ldmatrix lane offsets (element units) ----
    const int q = lane >> 3, rr8 = lane & 7;
    const int aoff = (rr8 + ((q & 1) << 3)) * LDSROW + ((q >> 1) << 3);

    float acc[4][4][4];
#pragma unroll
    for (int i = 0; i < 4; i++)
#pragma unroll
        for (int j = 0; j < 4; j++)
#pragma unroll
            for (int k = 0; k < 4; k++) acc[i][j][k] = 0.0f;

    const int nslab = K / BK;
    const uint4 zero4 = make_uint4(0u, 0u, 0u, 0u);

    // prologue
    uint4 vah = *(const uint4*)pAh;
    uint4 val = *(const uint4*)pAl;
    uint4 vwh = bv ? *(const uint4*)pWh : zero4;
    uint4 vwl = bv ? *(const uint4*)pWl : zero4;
    *(uint4*)&sAh[0][so] = vah;
    *(uint4*)&sAl[0][so] = val;
    *(uint4*)&sBh[0][so] = vwh;
    *(uint4*)&sBl[0][so] = vwl;
    __syncthreads();

    for (int s = 0; s < nslab; s++) {
        const int buf = s & 1;
        const bool more = (s + 1 < nslab);
        if (more) {
            const int off = (s + 1) * BK;
            vah = *(const uint4*)(pAh + off);
            val = *(const uint4*)(pAl + off);
            vwh = bv ? *(const uint4*)(pWh + off) : zero4;
            vwl = bv ? *(const uint4*)(pWl + off) : zero4;
        }

        uint32_t ah[4][4], al[4][4], bh[4][2], bl[4][2];
        const uint32_t bAh = (uint32_t)__cvta_generic_to_shared(&sAh[buf][0]);
        const uint32_t bAl = (uint32_t)__cvta_generic_to_shared(&sAl[buf][0]);
        const uint32_t bBh = (uint32_t)__cvta_generic_to_shared(&sBh[buf][0]);
        const uint32_t bBl = (uint32_t)__cvta_generic_to_shared(&sBl[buf][0]);
#pragma unroll
        for (int mi = 0; mi < 4; mi++) {
            const uint32_t eo = (uint32_t)(((wm * 64 + mi * 16) * LDSROW + aoff) * 2);
            ldsm_x4(ah[mi], bAh + eo);
            ldsm_x4(al[mi], bAl + eo);
        }
#pragma unroll
        for (int pn = 0; pn < 2; pn++) {
            const uint32_t eo = (uint32_t)(((wn * 32 + pn * 16) * LDSROW + aoff) * 2);
            uint32_t t[4];
            ldsm_x4(t, bBh + eo);
            bh[pn * 2][0]     = t[0]; bh[pn * 2][1]     = t[2];
            bh[pn * 2 + 1][0] = t[1]; bh[pn * 2 + 1][1] = t[3];
            ldsm_x4(t, bBl + eo);
            bl[pn * 2][0]     = t[0]; bl[pn * 2][1]     = t[2];
            bl[pn * 2 + 1][0] = t[1]; bl[pn * 2 + 1][1] = t[3];
        }

#pragma unroll
        for (int mi = 0; mi < 4; mi++)
#pragma unroll
            for (int ni = 0; ni < 4; ni++) {
                mma_bf16(acc[mi][ni], ah[mi], bh[ni]);
                mma_bf16(acc[mi][ni], ah[mi], bl[ni]);
                mma_bf16(acc[mi][ni], al[mi], bh[ni]);
            }

        if (more) {
            const int nb = buf ^ 1;
            *(uint4*)&sAh[nb][so] = vah;
            *(uint4*)&sAl[nb][so] = val;
            *(uint4*)&sBh[nb][so] = vwh;
            *(uint4*)&sBl[nb][so] = vwl;
            __syncthreads();
        }
    }

    // ---- epilogue ----
    const int g  = lane >> 2;
    const int tc = (lane & 3) << 1;
#pragma unroll
    for (int mi = 0; mi < 4; mi++) {
        const int mA = blockIdx.y * BM + wm * 64 + mi * 16 + g;
        const int mB = mA + 8;
        int rowA = mA, rowB = mB;
        if (MODE == 2) {
            rowA = (mA & ~1023) + permi(mA & 1023);
            rowB = (mB & ~1023) + permi(mB & 1023);
        }
#pragma unroll
        for (int ni = 0; ni < 4; ni++) {
            const int n0 = blockIdx.x * BN + wn * 32 + ni * 8 + tc;
            if (n0 < N) {
                float v0 = acc[mi][ni][0], v1 = acc[mi][ni][1];
                float v2 = acc[mi][ni][2], v3 = acc[mi][ni][3];
                if (MODE == 1) {
                    float2 bb = *(const float2*)&bias[n0];
                    v0 = softplusf(v0 + bb.x); v1 = softplusf(v1 + bb.y);
                    v2 = softplusf(v2 + bb.x); v3 = softplusf(v3 + bb.y);
                }
                if (MODE == 2) {
                    float2 bb = *(const float2*)&bias[n0];
                    float2 r0 = *(const float2*)&tokens[(size_t)rowA * ldc + n0];
                    float2 r1 = *(const float2*)&tokens[(size_t)rowB * ldc + n0];
                    v0 = geluf(v0 + bb.x) + r0.x; v1 = geluf(v1 + bb.y) + r0.y;
                    v2 = geluf(v2 + bb.x) + r1.x; v3 = geluf(v3 + bb.y) + r1.y;
                }
                *(float2*)&C[(size_t)rowA * ldc + n0] = make_float2(v0, v1);
                *(float2*)&C[(size_t)rowB * ldc + n0] = make_float2(v2, v3);
                if (BFOUT) {
                    __nv_bfloat16 h0, h1, h2, h3, l0, l1, l2, l3;
                    split_bf(v0, h0, l0); split_bf(v1, h1, l1);
                    split_bf(v2, h2, l2); split_bf(v3, h3, l3);
                    *(uint32_t*)&Ch[(size_t)rowA * ldc + n0] = pack2(h0, h1);
                    *(uint32_t*)&Cl[(size_t)rowA * ldc + n0] = pack2(l0, l1);
                    *(uint32_t*)&Ch[(size_t)rowB * ldc + n0] = pack2(h2, h3);
                    *(uint32_t*)&Cl[(size_t)rowB * ldc + n0] = pack2(l2, l3);
                }
            }
        }
    }
}

// ---------------- depthwise causal conv + bias + silu, emits fp32 + bf16 -----
__global__ void conv_silu_kernel(const float* __restrict__ conv_w,
                                 const float* __restrict__ conv_b)
{
    const int d  = threadIdx.x;            // 0..1023
    const int bt = blockIdx.x;             // 0..4095
    const int b = bt >> 10, t = bt & 1023;

    float w0 = conv_w[d * 4 + 0];
    float w1 = conv_w[d * 4 + 1];
    float w2 = conv_w[d * 4 + 2];
    float w3 = conv_w[d * 4 + 3];

    const size_t base = ((size_t)(b << 10)) * 2048 + d;
    float acc = conv_b[d];
    if (t - 3 >= 0) acc = fmaf(w0, g_XZ[base + (size_t)(t - 3) * 2048], acc);
    if (t - 2 >= 0) acc = fmaf(w1, g_XZ[base + (size_t)(t - 2) * 2048], acc);
    if (t - 1 >= 0) acc = fmaf(w2, g_XZ[base + (size_t)(t - 1) * 2048], acc);
    acc = fmaf(w3, g_XZ[base + (size_t)t * 2048], acc);

    float uu = siluf(acc);
    const size_t idx = (size_t)bt * DI + d;
    g_U[idx] = uu;
    __nv_bfloat16 h, l;
    split_bf(uu, h, l);
    g_Uh[idx] = h;
    g_Ul[idx] = l;
}

// ---------------- selective scan: warp per (b,d), lane = state --------------
__global__ void scan_kernel(const float* __restrict__ A_log,
                            const float* __restrict__ Dvec)
{
    const int warp = (blockIdx.x * blockDim.x + threadIdx.x) >> 5;  // 0..4095
    const int lane = threadIdx.x & 31;
    const int b = warp >> 10, d = warp & 1023;

    const float Aa = -__expf(A_log[d * DS + lane]);
    const float Dd = Dvec[d];

    float h = 0.0f;
    const int rowbase = b << 10;

    const float* pD = g_DELTA + (size_t)rowbase * DI + d;
    const float* pU = g_U     + (size_t)rowbase * DI + d;
    const float* pB = g_DBC   + (size_t)rowbase * DBCW + 32 + lane;
    const float* pC = pB + 32;

    for (int t0 = 0; t0 < L_; t0 += 32) {
        float yout = 0.0f;
#pragma unroll
        for (int s = 0; s < 32; s++) {
            const int t = t0 + s;
            float delta = __ldg(pD + (size_t)t * DI);
            float u     = __ldg(pU + (size_t)t * DI);
            float Bt    = __ldg(pB + (size_t)t * DBCW);
            float Ct    = __ldg(pC + (size_t)t * DBCW);

            float dA = __expf(delta * Aa);
            h = fmaf(dA, h, (delta * u) * Bt);

            float y = h * Ct;
#pragma unroll
            for (int o = 16; o; o >>= 1) y += __shfl_xor_sync(0xffffffffu, y, o);
            y = fmaf(u, Dd, y);
            if (lane == s) yout = y;
        }
        const int row = rowbase + t0 + lane;
        float z = g_XZ[(size_t)row * 2048 + 1024 + d];
        float v = yout * siluf(z);
        __nv_bfloat16 hh, ll;
        split_bf(v, hh, ll);
        const size_t idx = (size_t)row * DI + d;
        g_YAh[idx] = hh;
        g_YAl[idx] = ll;
    }
}

// ---------------- layernorm over 512, emits bf16 hi/lo -----------------------
__global__ void ln_kernel(const float* __restrict__ w,
                          const float* __restrict__ bvec)
{
    const int row = blockIdx.x;            // 0..4095
    const int tid = threadIdx.x;           // 256
    const float* y = g_Y2 + (size_t)row * DM;

    float v0 = y[tid], v1 = y[tid + 256];
    float s  = v0 + v1;
    float sq = v0 * v0 + v1 * v1;
#pragma unroll
    for (int o = 16; o; o >>= 1) {
        s  += __shfl_xor_sync(0xffffffffu, s,  o);
        sq += __shfl_xor_sync(0xffffffffu, sq, o);
    }
    __shared__ float ss[8], sqq[8];
    __shared__ float mu_s, rstd_s;
    if ((tid & 31) == 0) { ss[tid >> 5] = s; sqq[tid >> 5] = sq; }
    __syncthreads();
    if (tid == 0) {
        float S = 0.f, SQ = 0.f;
        for (int i = 0; i < 8; i++) { S += ss[i]; SQ += sqq[i]; }
        float mu  = S / 512.0f;
        float var = SQ / 512.0f - mu * mu;
        mu_s = mu;
        rstd_s = rsqrtf(var + 1e-5f);
    }
    __syncthreads();
    float mu = mu_s, rv = rstd_s;
    float a0 = (v0 - mu) * rv * w[tid]       + bvec[tid];
    float a1 = (v1 - mu) * rv * w[tid + 256] + bvec[tid + 256];
    __nv_bfloat16 h0, l0, h1, l1;
    split_bf(a0, h0, l0);
    split_bf(a1, h1, l1);
    g_YNh[(size_t)row * DM + tid]       = h0;
    g_YNl[(size_t)row * DM + tid]       = l0;
    g_YNh[(size_t)row * DM + tid + 256] = h1;
    g_YNl[(size_t)row * DM + tid + 256] = l1;
}

// ---------------- launch ------------------------------------------------------
static inline void cvt_launch(const float* src, __nv_bfloat16* h, __nv_bfloat16* l, int n) {
    int n4 = n / 4;
    cvt_kernel<<<(n4 + 255) / 256, 256>>>((const float4*)src, (uint2*)h, (uint2*)l, n4);
}

extern "C" void kernel_launch(void* const* d_in, const int* in_sizes, int n_in,
                              void* d_out, int out_size)
{
    const float* tokens     = (const float*)d_in[0];
    const float* in_proj_w  = (const float*)d_in[1];
    const float* conv_w     = (const float*)d_in[2];
    const float* conv_b     = (const float*)d_in[3];
    const float* x_proj_w   = (const float*)d_in[4];
    const float* dt_proj_w  = (const float*)d_in[5];
    const float* dt_proj_b  = (const float*)d_in[6];
    const float* A_log      = (const float*)d_in[7];
    const float* Dv         = (const float*)d_in[8];
    const float* out_proj_w = (const float*)d_in[9];
    const float* ln_w       = (const float*)d_in[10];
    const float* ln_b       = (const float*)d_in[11];
    const float* lin_w      = (const float*)d_in[12];
    const float* lin_b      = (const float*)d_in[13];
    float* out = (float*)d_out;

    float *XZ, *DBC, *DELTA, *Y2;
    cudaGetSymbolAddress((void**)&XZ,    g_XZ);
    cudaGetSymbolAddress((void**)&DBC,   g_DBC);
    cudaGetSymbolAddress((void**)&DELTA, g_DELTA);
    cudaGetSymbolAddress((void**)&Y2,    g_Y2);

    __nv_bfloat16 *TOKh, *TOKl, *W1h, *W1l, *W2h, *W2l, *W3h, *W3l, *W4h, *W4l, *W5h, *W5l;
    __nv_bfloat16 *Uh, *Ul, *DBCh, *DBCl, *YAh, *YAl, *YNh, *YNl;
    cudaGetSymbolAddress((void**)&TOKh, g_TOKh); cudaGetSymbolAddress((void**)&TOKl, g_TOKl);
    cudaGetSymbolAddress((void**)&W1h,  g_W1h);  cudaGetSymbolAddress((void**)&W1l,  g_W1l);
    cudaGetSymbolAddress((void**)&W2h,  g_W2h);  cudaGetSymbolAddress((void**)&W2l,  g_W2l);
    cudaGetSymbolAddress((void**)&W3h,  g_W3h);  cudaGetSymbolAddress((void**)&W3l,  g_W3l);
    cudaGetSymbolAddress((void**)&W4h,  g_W4h);  cudaGetSymbolAddress((void**)&W4l,  g_W4l);
    cudaGetSymbolAddress((void**)&W5h,  g_W5h);  cudaGetSymbolAddress((void**)&W5l,  g_W5l);
    cudaGetSymbolAddress((void**)&Uh,   g_Uh);   cudaGetSymbolAddress((void**)&Ul,   g_Ul);
    cudaGetSymbolAddress((void**)&DBCh, g_DBCh); cudaGetSymbolAddress((void**)&DBCl, g_DBCl);
    cudaGetSymbolAddress((void**)&YAh,  g_YAh);  cudaGetSymbolAddress((void**)&YAl,  g_YAl);
    cudaGetSymbolAddress((void**)&YNh,  g_YNh);  cudaGetSymbolAddress((void**)&YNl,  g_YNl);

    // 0) split tokens + weights into bf16 hi/lo planes
    cvt_launch(tokens,     TOKh, TOKl, NROWS * DM);
    cvt_launch(in_proj_w,  W1h,  W1l,  2048 * DM);
    cvt_launch(x_proj_w,   W2h,  W2l,  DBCW * DI);
    cvt_launch(dt_proj_w,  W3h,  W3l,  DI * DR);
    cvt_launch(out_proj_w, W4h,  W4l,  DM * DI);
    cvt_launch(lin_w,      W5h,  W5l,  DM * DM);

    // 1) xz = perm(tokens) @ in_proj^T      (4096 x 2048, K=512)
    tgemm<0, true, false><<<dim3(2048 / BN, NROWS / BM), 256>>>(
        TOKh, TOKl, DM, W1h, W1l, XZ, 2 * DI, NROWS, 2 * DI, DM,
        nullptr, nullptr, nullptr, nullptr);

    // 2) u = silu(causal depthwise conv(xm) + b)  (fp32 + bf16 planes)
    conv_silu_kernel<<<NROWS, DI>>>(conv_w, conv_b);

    // 3) dbc = u @ x_proj^T                 (4096 x 96, K=1024)  + bf16 planes
    tgemm<0, false, true><<<dim3(1, NROWS / BM), 256>>>(
        Uh, Ul, DI, W2h, W2l, DBC, DBCW, NROWS, DBCW, DI,
        nullptr, nullptr, DBCh, DBCl);

    // 4) delta = softplus(dt @ dt_proj^T + b)   (4096 x 1024, K=32)
    tgemm<1, false, false><<<dim3(1024 / BN, NROWS / BM), 256>>>(
        DBCh, DBCl, DBCW, W3h, W3l, DELTA, DI, NROWS, DI, DR,
        dt_proj_b, nullptr, nullptr, nullptr);

    // 5) selective scan + D skip + silu(z) gate  -> bf16 planes
    scan_kernel<<<1024, 128>>>(A_log, Dv);

    // 6) y2 = yact @ out_proj^T             (4096 x 512, K=1024)
    tgemm<0, false, false><<<dim3(512 / BN, NROWS / BM), 256>>>(
        YAh, YAl, DI, W4h, W4l, Y2, DM, NROWS, DM, DI,
        nullptr, nullptr, nullptr, nullptr);

    // 7) layernorm -> bf16 planes
    ln_kernel<<<NROWS, 256>>>(ln_w, ln_b);

    // 8) out = inv_perm( gelu(yn @ lin^T + b) + residual )
    tgemm<2, false, false><<<dim3(512 / BN, NROWS / BM), 256>>>(
        YNh, YNl, DM, W5h, W5l, out, DM, NROWS, DM, DM,
        lin_b, tokens, nullptr, nullptr);
}

// round 8
// speedup vs baseline: 2.8541x; 1.0932x over previous
#include <cuda_runtime.h>
#include <cuda_bf16.h>
#include <cstdint>
#include <math.h>

#define B_   4
#define L_   1024
#define DM   512
#define DI   1024
#define DS   32
#define DR   32
#define DBCW 96
#define NROWS (B_ * L_)   // 4096
#define SPLITK 8
#define KSEG  (DI / SPLITK)   // 128

// tensor GEMM tiling
#define BM 128
#define BN 128
#define BK 16
#define LDSROW 24   // bf16 elements per smem row (48 bytes, conflict-free ldmatrix)

// ---------------- fp32 scratch -----------------------------------------------
__device__ float g_XZ[NROWS * 2 * DI];    // xm | z
__device__ float g_U[NROWS * DI];         // silu(conv(xm))  (scan input)
__device__ float g_DBC[NROWS * DBCW];     // dt | B | C       (scan input)
__device__ float g_DBCP[SPLITK * NROWS * DBCW];  // split-K partials
__device__ float g_DELTA[NROWS * DI];     // softplus(...)    (scan input)
__device__ float g_Y2[NROWS * DM];        // out_proj output  (ln input)

// ---------------- bf16 hi/lo planes ------------------------------------------
__device__ __align__(16) __nv_bfloat16 g_TOKh[NROWS * DM],  g_TOKl[NROWS * DM];
__device__ __align__(16) __nv_bfloat16 g_W1h[2048 * DM],    g_W1l[2048 * DM];
__device__ __align__(16) __nv_bfloat16 g_W2h[DBCW * DI],    g_W2l[DBCW * DI];
__device__ __align__(16) __nv_bfloat16 g_W3h[DI * DR],      g_W3l[DI * DR];
__device__ __align__(16) __nv_bfloat16 g_W4h[DM * DI],      g_W4l[DM * DI];
__device__ __align__(16) __nv_bfloat16 g_W5h[DM * DM],      g_W5l[DM * DM];
__device__ __align__(16) __nv_bfloat16 g_Uh[NROWS * DI],    g_Ul[NROWS * DI];
__device__ __align__(16) __nv_bfloat16 g_DBCh[NROWS * DBCW],g_DBCl[NROWS * DBCW];
__device__ __align__(16) __nv_bfloat16 g_YAh[NROWS * DI],   g_YAl[NROWS * DI];
__device__ __align__(16) __nv_bfloat16 g_YNh[NROWS * DM],   g_YNl[NROWS * DM];

// snake permutation for H=W=32, mode 'tl_row'
__device__ __forceinline__ int permi(int i) {
    int r = i >> 5, c = i & 31;
    int col = (r & 1) ? (31 - c) : c;
    return (r << 5) | col;
}

__device__ __forceinline__ float siluf(float x) { return x / (1.0f + __expf(-x)); }
__device__ __forceinline__ float softplusf(float x) {
    return (x > 20.0f) ? x : log1pf(expf(x));
}
__device__ __forceinline__ float geluf(float x) {
    return 0.5f * x * (1.0f + erff(x * 0.70710678118654752f));
}

__device__ __forceinline__ void split_bf(float v, __nv_bfloat16& h, __nv_bfloat16& l) {
    h = __float2bfloat16(v);
    l = __float2bfloat16(v - __bfloat162float(h));
}
__device__ __forceinline__ uint32_t pack2(__nv_bfloat16 a, __nv_bfloat16 b) {
    return (uint32_t)__bfloat16_as_ushort(a) | ((uint32_t)__bfloat16_as_ushort(b) << 16);
}
__device__ __forceinline__ void cvt_hilo(float4 v, uint2& hw, uint2& lw) {
    __nv_bfloat16 h0, h1, h2, h3, l0, l1, l2, l3;
    split_bf(v.x, h0, l0); split_bf(v.y, h1, l1);
    split_bf(v.z, h2, l2); split_bf(v.w, h3, l3);
    hw.x = pack2(h0, h1); hw.y = pack2(h2, h3);
    lw.x = pack2(l0, l1); lw.y = pack2(l2, l3);
}

// ---- one merged conversion kernel for tokens + all weights ------------------
#define N4_TOK (NROWS * DM / 4)          // 524288
#define N4_W1  (2048 * DM / 4)           // 262144
#define N4_W2  (DBCW * DI / 4)           // 24576
#define N4_W3  (DI * DR / 4)             // 8192
#define N4_W4  (DM * DI / 4)             // 131072
#define N4_W5  (DM * DM / 4)             // 65536
#define N4_ALL (N4_TOK + N4_W1 + N4_W2 + N4_W3 + N4_W4 + N4_W5)

__global__ void cvt_all_kernel(
    const float4* __restrict__ s0, const float4* __restrict__ s1,
    const float4* __restrict__ s2, const float4* __restrict__ s3,
    const float4* __restrict__ s4, const float4* __restrict__ s5)
{
    int i = blockIdx.x * blockDim.x + threadIdx.x;
    const float4* s; uint2 *h, *l; int off;
    if      (i < N4_TOK)                          { s = s0; h = (uint2*)g_TOKh; l = (uint2*)g_TOKl; off = 0; }
    else if (i < N4_TOK+N4_W1)                    { s = s1; h = (uint2*)g_W1h;  l = (uint2*)g_W1l;  off = N4_TOK; }
    else if (i < N4_TOK+N4_W1+N4_W2)              { s = s2; h = (uint2*)g_W2h;  l = (uint2*)g_W2l;  off = N4_TOK+N4_W1; }
    else if (i < N4_TOK+N4_W1+N4_W2+N4_W3)        { s = s3; h = (uint2*)g_W3h;  l = (uint2*)g_W3l;  off = N4_TOK+N4_W1+N4_W2; }
    else if (i < N4_TOK+N4_W1+N4_W2+N4_W3+N4_W4)  { s = s4; h = (uint2*)g_W4h;  l = (uint2*)g_W4l;  off = N4_TOK+N4_W1+N4_W2+N4_W3; }
    else if (i < N4_ALL)                          { s = s5; h = (uint2*)g_W5h;  l = (uint2*)g_W5l;  off = N4_TOK+N4_W1+N4_W2+N4_W3+N4_W4; }
    else return;
    int j = i - off;
    uint2 hw, lw;
    cvt_hilo(s[j], hw, lw);
    h[j] = hw; l[j] = lw;
}

__device__ __forceinline__ void ldsm_x4(uint32_t* d, uint32_t saddr) {
    asm volatile("ldmatrix.sync.aligned.m8n8.x4.shared.b16 {%0,%1,%2,%3}, [%4];"
                 : "=r"(d[0]), "=r"(d[1]), "=r"(d[2]), "=r"(d[3]) : "r"(saddr));
}

__device__ __forceinline__ void mma_bf16(float* c, const uint32_t* a, const uint32_t* b) {
    asm volatile("mma.sync.aligned.m16n8k16.row.col.f32.bf16.bf16.f32 "
                 "{%0,%1,%2,%3}, {%4,%5,%6,%7}, {%8,%9}, {%0,%1,%2,%3};"
                 : "+f"(c[0]), "+f"(c[1]), "+f"(c[2]), "+f"(c[3])
                 : "r"(a[0]), "r"(a[1]), "r"(a[2]), "r"(a[3]), "r"(b[0]), "r"(b[1]));
}

// ---------------- tensor-core GEMM: C = A(MxK) * W(NxK)^T, bf16x3 ------------
// Pre-split bf16 hi/lo inputs; no conversion in the hot loop.
// K = segment length (loop bound); lda/ldw = full row strides.
// blockIdx.z = K-segment: koff = z*K, C += z*M*ldc (split-K partial outputs).
// MODE 0: plain fp32 store   MODE 1: softplus(acc+bias)   MODE 2: gelu(acc+bias)+tokens, permuted scatter
template<int MODE, bool PERMA>
__global__ __launch_bounds__(256, 2)
void tgemm(const __nv_bfloat16* __restrict__ Ah, const __nv_bfloat16* __restrict__ Al, int lda,
           const __nv_bfloat16* __restrict__ Wh, const __nv_bfloat16* __restrict__ Wl, int ldw,
           float* __restrict__ C, int ldc,
           int M, int N, int K,
           const float* __restrict__ bias,
           const float* __restrict__ tokens)
{
    __shared__ __align__(16) __nv_bfloat16 sAh[2][BM * LDSROW];
    __shared__ __align__(16) __nv_bfloat16 sAl[2][BM * LDSROW];
    __shared__ __align__(16) __nv_bfloat16 sBh[2][BN * LDSROW];
    __shared__ __align__(16) __nv_bfloat16 sBl[2][BN * LDSROW];

    const int tid  = threadIdx.x;
    const int lane = tid & 31;
    const int wid  = tid >> 5;
    const int wm   = wid >> 2;   // 0..1
    const int wn   = wid & 3;    // 0..3

    const int koff = blockIdx.z * K;
    float* Cp = C + (size_t)blockIdx.z * M * ldc;

    // ---- loader ----
    const int lr = tid >> 1;           // 0..127
    const int lk = (tid & 1) << 3;     // 0 or 8

    const int am = blockIdx.y * BM + lr;
    int arow = am;
    if (PERMA) arow = (am & ~1023) + permi(am & 1023);
    const __nv_bfloat16* pAh = Ah + (size_t)arow * lda + koff + lk;
    const __nv_bfloat16* pAl = Al + (size_t)arow * lda + koff + lk;

    const int nr = blockIdx.x * BN + lr;
    const bool bv = nr < N;
    const __nv_bfloat16* pWh = Wh + (size_t)(bv ? nr : 0) * ldw + koff + lk;
    const __nv_bfloat16* pWl = Wl + (size_t)(bv ? nr : 0) * ldw + koff + lk;

    const int so = lr * LDSROW + lk;

    // ---- ldmatrix lane offsets (element units) ----
    const int q = lane >> 3, rr8 = lane & 7;
    const int aoff = (rr8 + ((q & 1) << 3)) * LDSROW + ((q >> 1) << 3);

    float acc[4][4][4];
#pragma unroll
    for (int i = 0; i < 4; i++)
#pragma unroll
        for (int j = 0; j < 4; j++)
#pragma unroll
            for (int k = 0; k < 4; k++) acc[i][j][k] = 0.0f;

    const int nslab = K / BK;
    const uint4 zero4 = make_uint4(0u, 0u, 0u, 0u);

    // prologue
    uint4 vah = *(const uint4*)pAh;
    uint4 val = *(const uint4*)pAl;
    uint4 vwh = bv ? *(const uint4*)pWh : zero4;
    uint4 vwl = bv ? *(const uint4*)pWl : zero4;
    *(uint4*)&sAh[0][so] = vah;
    *(uint4*)&sAl[0][so] = val;
    *(uint4*)&sBh[0][so] = vwh;
    *(uint4*)&sBl[0][so] = vwl;
    __syncthreads();

    for (int s = 0; s < nslab; s++) {
        const int buf = s & 1;
        const bool more = (s + 1 < nslab);
        if (more) {
            const int off = (s + 1) * BK;
            vah = *(const uint4*)(pAh + off);
            val = *(const uint4*)(pAl + off);
            vwh = bv ? *(const uint4*)(pWh + off) : zero4;
            vwl = bv ? *(const uint4*)(pWl + off) : zero4;
        }

        uint32_t ah[4][4], al[4][4], bh[4][2], bl[4][2];
        const uint32_t bAh = (uint32_t)__cvta_generic_to_shared(&sAh[buf][0]);
        const uint32_t bAl = (uint32_t)__cvta_generic_to_shared(&sAl[buf][0]);
        const uint32_t bBh = (uint32_t)__cvta_generic_to_shared(&sBh[buf][0]);
        const uint32_t bBl = (uint32_t)__cvta_generic_to_shared(&sBl[buf][0]);
#pragma unroll
        for (int mi = 0; mi < 4; mi++) {
            const uint32_t eo = (uint32_t)(((wm * 64 + mi * 16) * LDSROW + aoff) * 2);
            ldsm_x4(ah[mi], bAh + eo);
            ldsm_x4(al[mi], bAl + eo);
        }
#pragma unroll
        for (int pn = 0; pn < 2; pn++) {
            const uint32_t eo = (uint32_t)(((wn * 32 + pn * 16) * LDSROW + aoff) * 2);
            uint32_t t[4];
            ldsm_x4(t, bBh + eo);
            bh[pn * 2][0]     = t[0]; bh[pn * 2][1]     = t[2];
            bh[pn * 2 + 1][0] = t[1]; bh[pn * 2 + 1][1] = t[3];
            ldsm_x4(t, bBl + eo);
            bl[pn * 2][0]     = t[0]; bl[pn * 2][1]     = t[2];
            bl[pn * 2 + 1][0] = t[1]; bl[pn * 2 + 1][1] = t[3];
        }

#pragma unroll
        for (int mi = 0; mi < 4; mi++)
#pragma unroll
            for (int ni = 0; ni < 4; ni++) {
                mma_bf16(acc[mi][ni], ah[mi], bh[ni]);
                mma_bf16(acc[mi][ni], ah[mi], bl[ni]);
                mma_bf16(acc[mi][ni], al[mi], bh[ni]);
            }

        if (more) {
            const int nb = buf ^ 1;
            *(uint4*)&sAh[nb][so] = vah;
            *(uint4*)&sAl[nb][so] = val;
            *(uint4*)&sBh[nb][so] = vwh;
            *(uint4*)&sBl[nb][so] = vwl;
            __syncthreads();
        }
    }

    // ---- epilogue ----
    const int g  = lane >> 2;
    const int tc = (lane & 3) << 1;
#pragma unroll
    for (int mi = 0; mi < 4; mi++) {
        const int mA = blockIdx.y * BM + wm * 64 + mi * 16 + g;
        const int mB = mA + 8;
        int rowA = mA, rowB = mB;
        if (MODE == 2) {
            rowA = (mA & ~1023) + permi(mA & 1023);
            rowB = (mB & ~1023) + permi(mB & 1023);
        }
#pragma unroll
        for (int ni = 0; ni < 4; ni++) {
            const int n0 = blockIdx.x * BN + wn * 32 + ni * 8 + tc;
            if (n0 < N) {
                float v0 = acc[mi][ni][0], v1 = acc[mi][ni][1];
                float v2 = acc[mi][ni][2], v3 = acc[mi][ni][3];
                if (MODE == 1) {
                    float2 bb = *(const float2*)&bias[n0];
                    v0 = softplusf(v0 + bb.x); v1 = softplusf(v1 + bb.y);
                    v2 = softplusf(v2 + bb.x); v3 = softplusf(v3 + bb.y);
                }
                if (MODE == 2) {
                    float2 bb = *(const float2*)&bias[n0];
                    float2 r0 = *(const float2*)&tokens[(size_t)rowA * ldc + n0];
                    float2 r1 = *(const float2*)&tokens[(size_t)rowB * ldc + n0];
                    v0 = geluf(v0 + bb.x) + r0.x; v1 = geluf(v1 + bb.y) + r0.y;
                    v2 = geluf(v2 + bb.x) + r1.x; v3 = geluf(v3 + bb.y) + r1.y;
                }
                *(float2*)&Cp[(size_t)rowA * ldc + n0] = make_float2(v0, v1);
                *(float2*)&Cp[(size_t)rowB * ldc + n0] = make_float2(v2, v3);
            }
        }
    }
}

// ---- split-K finalize: sum 8 partials -> g_DBC (fp32) + bf16 planes --------
__global__ void finalize_dbc_kernel()
{
    int i = blockIdx.x * blockDim.x + threadIdx.x;
    if (i >= NROWS * DBCW) return;
    float s = 0.0f;
#pragma unroll
    for (int z = 0; z < SPLITK; z++)
        s += g_DBCP[(size_t)z * NROWS * DBCW + i];
    g_DBC[i] = s;
    __nv_bfloat16 h, l;
    split_bf(s, h, l);
    g_DBCh[i] = h;
    g_DBCl[i] = l;
}

// ---------------- depthwise causal conv + bias + silu, emits fp32 + bf16 -----
__global__ void conv_silu_kernel(const float* __restrict__ conv_w,
                                 const float* __restrict__ conv_b)
{
    const int d  = threadIdx.x;            // 0..1023
    const int bt = blockIdx.x;             // 0..4095
    const int b = bt >> 10, t = bt & 1023;

    float w0 = conv_w[d * 4 + 0];
    float w1 = conv_w[d * 4 + 1];
    float w2 = conv_w[d * 4 + 2];
    float w3 = conv_w[d * 4 + 3];

    const size_t base = ((size_t)(b << 10)) * 2048 + d;
    float acc = conv_b[d];
    if (t - 3 >= 0) acc = fmaf(w0, g_XZ[base + (size_t)(t - 3) * 2048], acc);
    if (t - 2 >= 0) acc = fmaf(w1, g_XZ[base + (size_t)(t - 2) * 2048], acc);
    if (t - 1 >= 0) acc = fmaf(w2, g_XZ[base + (size_t)(t - 1) * 2048], acc);
    acc = fmaf(w3, g_XZ[base + (size_t)t * 2048], acc);

    float uu = siluf(acc);
    const size_t idx = (size_t)bt * DI + d;
    g_U[idx] = uu;
    __nv_bfloat16 h, l;
    split_bf(uu, h, l);
    g_Uh[idx] = h;
    g_Ul[idx] = l;
}

// ---------------- selective scan: warp per (b,d), lane = state --------------
__global__ void scan_kernel(const float* __restrict__ A_log,
                            const float* __restrict__ Dvec)
{
    const int warp = (blockIdx.x * blockDim.x + threadIdx.x) >> 5;  // 0..4095
    const int lane = threadIdx.x & 31;
    const int b = warp >> 10, d = warp & 1023;

    const float Aa = -__expf(A_log[d * DS + lane]);
    const float Dd = Dvec[d];

    float h = 0.0f;
    const int rowbase = b << 10;

    const float* pD = g_DELTA + (size_t)rowbase * DI + d;
    const float* pU = g_U     + (size_t)rowbase * DI + d;
    const float* pB = g_DBC   + (size_t)rowbase * DBCW + 32 + lane;
    const float* pC = pB + 32;

    for (int t0 = 0; t0 < L_; t0 += 32) {
        float yout = 0.0f;
#pragma unroll
        for (int s = 0; s < 32; s++) {
            const int t = t0 + s;
            float delta = __ldg(pD + (size_t)t * DI);
            float u     = __ldg(pU + (size_t)t * DI);
            float Bt    = __ldg(pB + (size_t)t * DBCW);
            float Ct    = __ldg(pC + (size_t)t * DBCW);

            float dA = __expf(delta * Aa);
            h = fmaf(dA, h, (delta * u) * Bt);

            float y = h * Ct;
#pragma unroll
            for (int o = 16; o; o >>= 1) y += __shfl_xor_sync(0xffffffffu, y, o);
            y = fmaf(u, Dd, y);
            if (lane == s) yout = y;
        }
        const int row = rowbase + t0 + lane;
        float z = g_XZ[(size_t)row * 2048 + 1024 + d];
        float v = yout * siluf(z);
        __nv_bfloat16 hh, ll;
        split_bf(v, hh, ll);
        const size_t idx = (size_t)row * DI + d;
        g_YAh[idx] = hh;
        g_YAl[idx] = ll;
    }
}

// ---------------- layernorm over 512, emits bf16 hi/lo -----------------------
__global__ void ln_kernel(const float* __restrict__ w,
                          const float* __restrict__ bvec)
{
    const int row = blockIdx.x;            // 0..4095
    const int tid = threadIdx.x;           // 256
    const float* y = g_Y2 + (size_t)row * DM;

    float v0 = y[tid], v1 = y[tid + 256];
    float s  = v0 + v1;
    float sq = v0 * v0 + v1 * v1;
#pragma unroll
    for (int o = 16; o; o >>= 1) {
        s  += __shfl_xor_sync(0xffffffffu, s,  o);
        sq += __shfl_xor_sync(0xffffffffu, sq, o);
    }
    __shared__ float ss[8], sqq[8];
    __shared__ float mu_s, rstd_s;
    if ((tid & 31) == 0) { ss[tid >> 5] = s; sqq[tid >> 5] = sq; }
    __syncthreads();
    if (tid == 0) {
        float S = 0.f, SQ = 0.f;
        for (int i = 0; i < 8; i++) { S += ss[i]; SQ += sqq[i]; }
        float mu  = S / 512.0f;
        float var = SQ / 512.0f - mu * mu;
        mu_s = mu;
        rstd_s = rsqrtf(var + 1e-5f);
    }
    __syncthreads();
    float mu = mu_s, rv = rstd_s;
    float a0 = (v0 - mu) * rv * w[tid]       + bvec[tid];
    float a1 = (v1 - mu) * rv * w[tid + 256] + bvec[tid + 256];
    __nv_bfloat16 h0, l0, h1, l1;
    split_bf(a0, h0, l0);
    split_bf(a1, h1, l1);
    g_YNh[(size_t)row * DM + tid]       = h0;
    g_YNl[(size_t)row * DM + tid]       = l0;
    g_YNh[(size_t)row * DM + tid + 256] = h1;
    g_YNl[(size_t)row * DM + tid + 256] = l1;
}

// ---------------- launch ------------------------------------------------------
extern "C" void kernel_launch(void* const* d_in, const int* in_sizes, int n_in,
                              void* d_out, int out_size)
{
    const float* tokens     = (const float*)d_in[0];
    const float* in_proj_w  = (const float*)d_in[1];
    const float* conv_w     = (const float*)d_in[2];
    const float* conv_b     = (const float*)d_in[3];
    const float* x_proj_w   = (const float*)d_in[4];
    const float* dt_proj_w  = (const float*)d_in[5];
    const float* dt_proj_b  = (const float*)d_in[6];
    const float* A_log      = (const float*)d_in[7];
    const float* Dv         = (const float*)d_in[8];
    const float* out_proj_w = (const float*)d_in[9];
    const float* ln_w       = (const float*)d_in[10];
    const float* ln_b       = (const float*)d_in[11];
    const float* lin_w      = (const float*)d_in[12];
    const float* lin_b      = (const float*)d_in[13];
    float* out = (float*)d_out;

    float *XZ, *DELTA, *Y2, *DBCP;
    cudaGetSymbolAddress((void**)&XZ,    g_XZ);
    cudaGetSymbolAddress((void**)&DELTA, g_DELTA);
    cudaGetSymbolAddress((void**)&Y2,    g_Y2);
    cudaGetSymbolAddress((void**)&DBCP,  g_DBCP);

    __nv_bfloat16 *TOKh, *TOKl, *W1h, *W1l, *W2h, *W2l, *W3h, *W3l, *W4h, *W4l, *W5h, *W5l;
    __nv_bfloat16 *Uh, *Ul, *DBCh, *DBCl, *YAh, *YAl, *YNh, *YNl;
    cudaGetSymbolAddress((void**)&TOKh, g_TOKh); cudaGetSymbolAddress((void**)&TOKl, g_TOKl);
    cudaGetSymbolAddress((void**)&W1h,  g_W1h);  cudaGetSymbolAddress((void**)&W1l,  g_W1l);
    cudaGetSymbolAddress((void**)&W2h,  g_W2h);  cudaGetSymbolAddress((void**)&W2l,  g_W2l);
    cudaGetSymbolAddress((void**)&W3h,  g_W3h);  cudaGetSymbolAddress((void**)&W3l,  g_W3l);
    cudaGetSymbolAddress((void**)&W4h,  g_W4h);  cudaGetSymbolAddress((void**)&W4l,  g_W4l);
    cudaGetSymbolAddress((void**)&W5h,  g_W5h);  cudaGetSymbolAddress((void**)&W5l,  g_W5l);
    cudaGetSymbolAddress((void**)&Uh,   g_Uh);   cudaGetSymbolAddress((void**)&Ul,   g_Ul);
    cudaGetSymbolAddress((void**)&DBCh, g_DBCh); cudaGetSymbolAddress((void**)&DBCl, g_DBCl);
    cudaGetSymbolAddress((void**)&YAh,  g_YAh);  cudaGetSymbolAddress((void**)&YAl,  g_YAl);
    cudaGetSymbolAddress((void**)&YNh,  g_YNh);  cudaGetSymbolAddress((void**)&YNl,  g_YNl);

    // 0) one merged kernel: split tokens + all weights into bf16 hi/lo planes
    cvt_all_kernel<<<(N4_ALL + 255) / 256, 256>>>(
        (const float4*)tokens, (const float4*)in_proj_w, (const float4*)x_proj_w,
        (const float4*)dt_proj_w, (const float4*)out_proj_w, (const float4*)lin_w);

    // 1) xz = perm(tokens) @ in_proj^T      (4096 x 2048, K=512)
    tgemm<0, true><<<dim3(2048 / BN, NROWS / BM), 256>>>(
        TOKh, TOKl, DM, W1h, W1l, DM, XZ, 2 * DI, NROWS, 2 * DI, DM,
        nullptr, nullptr);

    // 2) u = silu(causal depthwise conv(xm) + b)
    conv_silu_kernel<<<NROWS, DI>>>(conv_w, conv_b);

    // 3) dbc = u @ x_proj^T  (4096 x 96, K=1024) -- split-K x8 for full-chip
    tgemm<0, false><<<dim3(1, NROWS / BM, SPLITK), 256>>>(
        Uh, Ul, DI, W2h, W2l, DI, DBCP, DBCW, NROWS, DBCW, KSEG,
        nullptr, nullptr);
    finalize_dbc_kernel<<<(NROWS * DBCW + 255) / 256, 256>>>();

    // 4) delta = softplus(dt @ dt_proj^T + b)   (4096 x 1024, K=32)
    tgemm<1, false><<<dim3(1024 / BN, NROWS / BM), 256>>>(
        DBCh, DBCl, DBCW, W3h, W3l, DR, DELTA, DI, NROWS, DI, DR,
        dt_proj_b, nullptr);

    // 5) selective scan + D skip + silu(z) gate  -> bf16 planes
    scan_kernel<<<1024, 128>>>(A_log, Dv);

    // 6) y2 = yact @ out_proj^T             (4096 x 512, K=1024)
    tgemm<0, false><<<dim3(512 / BN, NROWS / BM), 256>>>(
        YAh, YAl, DI, W4h, W4l, DI, Y2, DM, NROWS, DM, DI,
        nullptr, nullptr);

    // 7) layernorm -> bf16 planes
    ln_kernel<<<NROWS, 256>>>(ln_w, ln_b);

    // 8) out = inv_perm( gelu(yn @ lin^T + b) + residual )
    tgemm<2, false><<<dim3(512 / BN, NROWS / BM), 256>>>(
        YNh, YNl, DM, W5h, W5l, DM, out, DM, NROWS, DM, DM,
        lin_b, tokens);
}

// round 9
// speedup vs baseline: 2.9403x; 1.0302x over previous
#include <cuda_runtime.h>
#include <cuda_bf16.h>
#include <cstdint>
#include <math.h>

#define B_   4
#define L_   1024
#define DM   512
#define DI   1024
#define DS   32
#define DR   32
#define DBCW 96
#define NROWS (B_ * L_)   // 4096
#define SPLITK 8
#define KSEG  (DI / SPLITK)   // 128

// tensor GEMM tiling
#define BM 128
#define BN 128
#define BK 16
#define LDSROW 24   // bf16 elements per smem row (48 bytes, conflict-free ldmatrix)

// ---------------- fp32 scratch -----------------------------------------------
__device__ float g_XZ[NROWS * 2 * DI];    // xm | z
__device__ float g_U[NROWS * DI];         // silu(conv(xm))  (scan input)
__device__ float g_DBC[NROWS * DBCW];     // dt | B | C       (scan input)
__device__ float g_DBCP[SPLITK * NROWS * DBCW];  // split-K partials
__device__ float g_DELTA[NROWS * DI];     // softplus(...)    (scan input)
__device__ float g_Y2[NROWS * DM];        // out_proj output  (ln input)

// ---------------- bf16 hi/lo planes ------------------------------------------
__device__ __align__(16) __nv_bfloat16 g_TOKh[NROWS * DM],  g_TOKl[NROWS * DM];
__device__ __align__(16) __nv_bfloat16 g_W1h[2048 * DM],    g_W1l[2048 * DM];
__device__ __align__(16) __nv_bfloat16 g_W2h[DBCW * DI],    g_W2l[DBCW * DI];
__device__ __align__(16) __nv_bfloat16 g_W3h[DI * DR],      g_W3l[DI * DR];
__device__ __align__(16) __nv_bfloat16 g_W4h[DM * DI],      g_W4l[DM * DI];
__device__ __align__(16) __nv_bfloat16 g_W5h[DM * DM],      g_W5l[DM * DM];
__device__ __align__(16) __nv_bfloat16 g_Uh[NROWS * DI],    g_Ul[NROWS * DI];
__device__ __align__(16) __nv_bfloat16 g_DBCh[NROWS * DBCW],g_DBCl[NROWS * DBCW];
__device__ __align__(16) __nv_bfloat16 g_YAh[NROWS * DI],   g_YAl[NROWS * DI];
__device__ __align__(16) __nv_bfloat16 g_YNh[NROWS * DM],   g_YNl[NROWS * DM];

// snake permutation for H=W=32, mode 'tl_row'
__device__ __forceinline__ int permi(int i) {
    int r = i >> 5, c = i & 31;
    int col = (r & 1) ? (31 - c) : c;
    return (r << 5) | col;
}

__device__ __forceinline__ float siluf(float x) { return x / (1.0f + __expf(-x)); }
__device__ __forceinline__ float softplusf(float x) {
    return (x > 20.0f) ? x : log1pf(expf(x));
}
__device__ __forceinline__ float geluf(float x) {
    return 0.5f * x * (1.0f + erff(x * 0.70710678118654752f));
}

__device__ __forceinline__ void split_bf(float v, __nv_bfloat16& h, __nv_bfloat16& l) {
    h = __float2bfloat16(v);
    l = __float2bfloat16(v - __bfloat162float(h));
}
__device__ __forceinline__ uint32_t pack2(__nv_bfloat16 a, __nv_bfloat16 b) {
    return (uint32_t)__bfloat16_as_ushort(a) | ((uint32_t)__bfloat16_as_ushort(b) << 16);
}
__device__ __forceinline__ void cvt_hilo(float4 v, uint2& hw, uint2& lw) {
    __nv_bfloat16 h0, h1, h2, h3, l0, l1, l2, l3;
    split_bf(v.x, h0, l0); split_bf(v.y, h1, l1);
    split_bf(v.z, h2, l2); split_bf(v.w, h3, l3);
    hw.x = pack2(h0, h1); hw.y = pack2(h2, h3);
    lw.x = pack2(l0, l1); lw.y = pack2(l2, l3);
}

// ---- one merged conversion kernel for tokens + all weights ------------------
#define N4_TOK (NROWS * DM / 4)          // 524288
#define N4_W1  (2048 * DM / 4)           // 262144
#define N4_W2  (DBCW * DI / 4)           // 24576
#define N4_W3  (DI * DR / 4)             // 8192
#define N4_W4  (DM * DI / 4)             // 131072
#define N4_W5  (DM * DM / 4)             // 65536
#define N4_ALL (N4_TOK + N4_W1 + N4_W2 + N4_W3 + N4_W4 + N4_W5)

__global__ void cvt_all_kernel(
    const float4* __restrict__ s0, const float4* __restrict__ s1,
    const float4* __restrict__ s2, const float4* __restrict__ s3,
    const float4* __restrict__ s4, const float4* __restrict__ s5)
{
    int i = blockIdx.x * blockDim.x + threadIdx.x;
    const float4* s; uint2 *h, *l; int off;
    if      (i < N4_TOK)                          { s = s0; h = (uint2*)g_TOKh; l = (uint2*)g_TOKl; off = 0; }
    else if (i < N4_TOK+N4_W1)                    { s = s1; h = (uint2*)g_W1h;  l = (uint2*)g_W1l;  off = N4_TOK; }
    else if (i < N4_TOK+N4_W1+N4_W2)              { s = s2; h = (uint2*)g_W2h;  l = (uint2*)g_W2l;  off = N4_TOK+N4_W1; }
    else if (i < N4_TOK+N4_W1+N4_W2+N4_W3)        { s = s3; h = (uint2*)g_W3h;  l = (uint2*)g_W3l;  off = N4_TOK+N4_W1+N4_W2; }
    else if (i < N4_TOK+N4_W1+N4_W2+N4_W3+N4_W4)  { s = s4; h = (uint2*)g_W4h;  l = (uint2*)g_W4l;  off = N4_TOK+N4_W1+N4_W2+N4_W3; }
    else if (i < N4_ALL)                          { s = s5; h = (uint2*)g_W5h;  l = (uint2*)g_W5l;  off = N4_TOK+N4_W1+N4_W2+N4_W3+N4_W4; }
    else return;
    int j = i - off;
    uint2 hw, lw;
    cvt_hilo(s[j], hw, lw);
    h[j] = hw; l[j] = lw;
}

__device__ __forceinline__ void ldsm_x4(uint32_t* d, uint32_t saddr) {
    asm volatile("ldmatrix.sync.aligned.m8n8.x4.shared.b16 {%0,%1,%2,%3}, [%4];"
                 : "=r"(d[0]), "=r"(d[1]), "=r"(d[2]), "=r"(d[3]) : "r"(saddr));
}

__device__ __forceinline__ void mma_bf16(float* c, const uint32_t* a, const uint32_t* b) {
    asm volatile("mma.sync.aligned.m16n8k16.row.col.f32.bf16.bf16.f32 "
                 "{%0,%1,%2,%3}, {%4,%5,%6,%7}, {%8,%9}, {%0,%1,%2,%3};"
                 : "+f"(c[0]), "+f"(c[1]), "+f"(c[2]), "+f"(c[3])
                 : "r"(a[0]), "r"(a[1]), "r"(a[2]), "r"(a[3]), "r"(b[0]), "r"(b[1]));
}

// ---------------- tensor-core GEMM: C = A(MxK) * W(NxK)^T, bf16x3 ------------
// Pre-split bf16 hi/lo inputs; no conversion in the hot loop.
// blockIdx.z = K-segment: koff = z*K, C += z*M*ldc (split-K partial outputs).
// MODE 0: plain fp32 store   MODE 1: softplus(acc+bias)   MODE 2: gelu(acc+bias)+tokens, permuted scatter
template<int MODE, bool PERMA>
__global__ __launch_bounds__(256, 2)
void tgemm(const __nv_bfloat16* __restrict__ Ah, const __nv_bfloat16* __restrict__ Al, int lda,
           const __nv_bfloat16* __restrict__ Wh, const __nv_bfloat16* __restrict__ Wl, int ldw,
           float* __restrict__ C, int ldc,
           int M, int N, int K,
           const float* __restrict__ bias,
           const float* __restrict__ tokens)
{
    __shared__ __align__(16) __nv_bfloat16 sAh[2][BM * LDSROW];
    __shared__ __align__(16) __nv_bfloat16 sAl[2][BM * LDSROW];
    __shared__ __align__(16) __nv_bfloat16 sBh[2][BN * LDSROW];
    __shared__ __align__(16) __nv_bfloat16 sBl[2][BN * LDSROW];

    const int tid  = threadIdx.x;
    const int lane = tid & 31;
    const int wid  = tid >> 5;
    const int wm   = wid >> 2;   // 0..1
    const int wn   = wid & 3;    // 0..3

    const int koff = blockIdx.z * K;
    float* Cp = C + (size_t)blockIdx.z * M * ldc;

    // ---- loader ----
    const int lr = tid >> 1;           // 0..127
    const int lk = (tid & 1) << 3;     // 0 or 8

    const int am = blockIdx.y * BM + lr;
    int arow = am;
    if (PERMA) arow = (am & ~1023) + permi(am & 1023);
    const __nv_bfloat16* pAh = Ah + (size_t)arow * lda + koff + lk;
    const __nv_bfloat16* pAl = Al + (size_t)arow * lda + koff + lk;

    const int nr = blockIdx.x * BN + lr;
    const bool bv = nr < N;
    const __nv_bfloat16* pWh = Wh + (size_t)(bv ? nr : 0) * ldw + koff + lk;
    const __nv_bfloat16* pWl = Wl + (size_t)(bv ? nr : 0) * ldw + koff + lk;

    const int so = lr * LDSROW + lk;

    // ---- ldmatrix lane offsets (element units) ----
    const int q = lane >> 3, rr8 = lane & 7;
    const int aoff = (rr8 + ((q & 1) << 3)) * LDSROW + ((q >> 1) << 3);

    float acc[4][4][4];
#pragma unroll
    for (int i = 0; i < 4; i++)
#pragma unroll
        for (int j = 0; j < 4; j++)
#pragma unroll
            for (int k = 0; k < 4; k++) acc[i][j][k] = 0.0f;

    const int nslab = K / BK;
    const uint4 zero4 = make_uint4(0u, 0u, 0u, 0u);

    // prologue
    uint4 vah = *(const uint4*)pAh;
    uint4 val = *(const uint4*)pAl;
    uint4 vwh = bv ? *(const uint4*)pWh : zero4;
    uint4 vwl = bv ? *(const uint4*)pWl : zero4;
    *(uint4*)&sAh[0][so] = vah;
    *(uint4*)&sAl[0][so] = val;
    *(uint4*)&sBh[0][so] = vwh;
    *(uint4*)&sBl[0][so] = vwl;
    __syncthreads();

    for (int s = 0; s < nslab; s++) {
        const int buf = s & 1;
        const bool more = (s + 1 < nslab);
        if (more) {
            const int off = (s + 1) * BK;
            vah = *(const uint4*)(pAh + off);
            val = *(const uint4*)(pAl + off);
            vwh = bv ? *(const uint4*)(pWh + off) : zero4;
            vwl = bv ? *(const uint4*)(pWl + off) : zero4;
        }

        uint32_t ah[4][4], al[4][4], bh[4][2], bl[4][2];
        const uint32_t bAh = (uint32_t)__cvta_generic_to_shared(&sAh[buf][0]);
        const uint32_t bAl = (uint32_t)__cvta_generic_to_shared(&sAl[buf][0]);
        const uint32_t bBh = (uint32_t)__cvta_generic_to_shared(&sBh[buf][0]);
        const uint32_t bBl = (uint32_t)__cvta_generic_to_shared(&sBl[buf][0]);
#pragma unroll
        for (int mi = 0; mi < 4; mi++) {
            const uint32_t eo = (uint32_t)(((wm * 64 + mi * 16) * LDSROW + aoff) * 2);
            ldsm_x4(ah[mi], bAh + eo);
            ldsm_x4(al[mi], bAl + eo);
        }
#pragma unroll
        for (int pn = 0; pn < 2; pn++) {
            const uint32_t eo = (uint32_t)(((wn * 32 + pn * 16) * LDSROW + aoff) * 2);
            uint32_t t[4];
            ldsm_x4(t, bBh + eo);
            bh[pn * 2][0]     = t[0]; bh[pn * 2][1]     = t[2];
            bh[pn * 2 + 1][0] = t[1]; bh[pn * 2 + 1][1] = t[3];
            ldsm_x4(t, bBl + eo);
            bl[pn * 2][0]     = t[0]; bl[pn * 2][1]     = t[2];
            bl[pn * 2 + 1][0] = t[1]; bl[pn * 2 + 1][1] = t[3];
        }

#pragma unroll
        for (int mi = 0; mi < 4; mi++)
#pragma unroll
            for (int ni = 0; ni < 4; ni++) {
                mma_bf16(acc[mi][ni], ah[mi], bh[ni]);
                mma_bf16(acc[mi][ni], ah[mi], bl[ni]);
                mma_bf16(acc[mi][ni], al[mi], bh[ni]);
            }

        if (more) {
            const int nb = buf ^ 1;
            *(uint4*)&sAh[nb][so] = vah;
            *(uint4*)&sAl[nb][so] = val;
            *(uint4*)&sBh[nb][so] = vwh;
            *(uint4*)&sBl[nb][so] = vwl;
            __syncthreads();
        }
    }

    // ---- epilogue ----
    const int g  = lane >> 2;
    const int tc = (lane & 3) << 1;
#pragma unroll
    for (int mi = 0; mi < 4; mi++) {
        const int mA = blockIdx.y * BM + wm * 64 + mi * 16 + g;
        const int mB = mA + 8;
        int rowA = mA, rowB = mB;
        if (MODE == 2) {
            rowA = (mA & ~1023) + permi(mA & 1023);
            rowB = (mB & ~1023) + permi(mB & 1023);
        }
#pragma unroll
        for (int ni = 0; ni < 4; ni++) {
            const int n0 = blockIdx.x * BN + wn * 32 + ni * 8 + tc;
            if (n0 < N) {
                float v0 = acc[mi][ni][0], v1 = acc[mi][ni][1];
                float v2 = acc[mi][ni][2], v3 = acc[mi][ni][3];
                if (MODE == 1) {
                    float2 bb = *(const float2*)&bias[n0];
                    v0 = softplusf(v0 + bb.x); v1 = softplusf(v1 + bb.y);
                    v2 = softplusf(v2 + bb.x); v3 = softplusf(v3 + bb.y);
                }
                if (MODE == 2) {
                    float2 bb = *(const float2*)&bias[n0];
                    float2 r0 = *(const float2*)&tokens[(size_t)rowA * ldc + n0];
                    float2 r1 = *(const float2*)&tokens[(size_t)rowB * ldc + n0];
                    v0 = geluf(v0 + bb.x) + r0.x; v1 = geluf(v1 + bb.y) + r0.y;
                    v2 = geluf(v2 + bb.x) + r1.x; v3 = geluf(v3 + bb.y) + r1.y;
                }
                *(float2*)&Cp[(size_t)rowA * ldc + n0] = make_float2(v0, v1);
                *(float2*)&Cp[(size_t)rowB * ldc + n0] = make_float2(v2, v3);
            }
        }
    }
}

// ---- split-K finalize: sum 8 partials -> g_DBC (fp32) + bf16 planes --------
__global__ void finalize_dbc_kernel()
{
    int i = blockIdx.x * blockDim.x + threadIdx.x;
    if (i >= NROWS * DBCW) return;
    float s = 0.0f;
#pragma unroll
    for (int z = 0; z < SPLITK; z++)
        s += g_DBCP[(size_t)z * NROWS * DBCW + i];
    g_DBC[i] = s;
    __nv_bfloat16 h, l;
    split_bf(s, h, l);
    g_DBCh[i] = h;
    g_DBCl[i] = l;
}

// ---------------- depthwise causal conv + bias + silu, emits fp32 + bf16 -----
__global__ void conv_silu_kernel(const float* __restrict__ conv_w,
                                 const float* __restrict__ conv_b)
{
    const int d  = threadIdx.x;            // 0..1023
    const int bt = blockIdx.x;             // 0..4095
    const int b = bt >> 10, t = bt & 1023;

    float w0 = conv_w[d * 4 + 0];
    float w1 = conv_w[d * 4 + 1];
    float w2 = conv_w[d * 4 + 2];
    float w3 = conv_w[d * 4 + 3];

    const size_t base = ((size_t)(b << 10)) * 2048 + d;
    float acc = conv_b[d];
    if (t - 3 >= 0) acc = fmaf(w0, g_XZ[base + (size_t)(t - 3) * 2048], acc);
    if (t - 2 >= 0) acc = fmaf(w1, g_XZ[base + (size_t)(t - 2) * 2048], acc);
    if (t - 1 >= 0) acc = fmaf(w2, g_XZ[base + (size_t)(t - 1) * 2048], acc);
    acc = fmaf(w3, g_XZ[base + (size_t)t * 2048], acc);

    float uu = siluf(acc);
    const size_t idx = (size_t)bt * DI + d;
    g_U[idx] = uu;
    __nv_bfloat16 h, l;
    split_bf(uu, h, l);
    g_Uh[idx] = h;
    g_Ul[idx] = l;
}

// ---------------- selective scan v3 ------------------------------------------
// Block = 256 threads = 8 warps = 8 CONSECUTIVE channels (same batch).
// Warp w handles channel d0+w; lane = state. Per 32-step chunk:
//   - main loop: h recurrence only, v[s] = h*C (+ lane0-masked u*D). No reduction.
//   - transpose-reduce: 31 shuffles -> lane l holds y(t0+l).
//   - coalesced epilogue via smem: z-gate + bf16 split + store, 8 channels wide.
__global__ __launch_bounds__(256)
void scan_kernel(const float* __restrict__ A_log,
                 const float* __restrict__ Dvec)
{
    __shared__ float sy[8][36];

    const int tid  = threadIdx.x;
    const int lane = tid & 31;
    const int wid  = tid >> 5;        // 0..7
    const int b    = blockIdx.x >> 7;             // 0..3  (128 blocks per batch)
    const int d0   = (blockIdx.x & 127) << 3;     // 0,8,...,1016
    const int d    = d0 + wid;

    const float Aa  = -__expf(A_log[d * DS + lane]);
    const float dd0 = (lane == 0) ? Dvec[d] : 0.0f;   // u*D folded into lane0 partial

    float h = 0.0f;
    const int rowbase = b << 10;

    const float* pD = g_DELTA + (size_t)rowbase * DI + d;
    const float* pU = g_U     + (size_t)rowbase * DI + d;
    const float* pB = g_DBC   + (size_t)rowbase * DBCW + 32 + lane;
    const float* pC = pB + 32;

    for (int t0 = 0; t0 < L_; t0 += 32) {
        float v[32];
#pragma unroll
        for (int s = 0; s < 32; s++) {
            const int t = t0 + s;
            float delta = __ldg(pD + (size_t)t * DI);     // broadcast
            float u     = __ldg(pU + (size_t)t * DI);     // broadcast
            float Bt    = __ldg(pB + (size_t)t * DBCW);   // coalesced
            float Ct    = __ldg(pC + (size_t)t * DBCW);   // coalesced

            float dA = __expf(delta * Aa);
            h = fmaf(dA, h, (delta * u) * Bt);
            v[s] = fmaf(u, dd0, h * Ct);
        }

        // transpose-reduce: after this, lane l holds sum over states for step t0+l
#pragma unroll
        for (int off = 16; off; off >>= 1) {
            const bool hi = (lane & off) != 0;
#pragma unroll
            for (int k = 0; k < off; k++) {
                float send = hi ? v[k] : v[k + off];
                float recv = __shfl_xor_sync(0xffffffffu, send, off);
                v[k] = (hi ? v[k + off] : v[k]) + recv;
            }
        }

        // stage y into smem, then coalesced gate+store across 8 channels
        sy[wid][lane] = v[0];
        __syncthreads();
        {
            const int st = tid >> 3;          // 0..31
            const int c  = tid & 7;           // 0..7
            const int row = rowbase + t0 + st;
            float y = sy[c][st];
            float z = g_XZ[(size_t)row * 2048 + 1024 + d0 + c];
            float val = y * siluf(z);
            __nv_bfloat16 hh, ll;
            split_bf(val, hh, ll);
            const size_t idx = (size_t)row * DI + d0 + c;
            g_YAh[idx] = hh;
            g_YAl[idx] = ll;
        }
        __syncthreads();
    }
}

// ---------------- layernorm over 512, emits bf16 hi/lo -----------------------
__global__ void ln_kernel(const float* __restrict__ w,
                          const float* __restrict__ bvec)
{
    const int row = blockIdx.x;            // 0..4095
    const int tid = threadIdx.x;           // 256
    const float* y = g_Y2 + (size_t)row * DM;

    float v0 = y[tid], v1 = y[tid + 256];
    float s  = v0 + v1;
    float sq = v0 * v0 + v1 * v1;
#pragma unroll
    for (int o = 16; o; o >>= 1) {
        s  += __shfl_xor_sync(0xffffffffu, s,  o);
        sq += __shfl_xor_sync(0xffffffffu, sq, o);
    }
    __shared__ float ss[8], sqq[8];
    __shared__ float mu_s, rstd_s;
    if ((tid & 31) == 0) { ss[tid >> 5] = s; sqq[tid >> 5] = sq; }
    __syncthreads();
    if (tid == 0) {
        float S = 0.f, SQ = 0.f;
        for (int i = 0; i < 8; i++) { S += ss[i]; SQ += sqq[i]; }
        float mu  = S / 512.0f;
        float var = SQ / 512.0f - mu * mu;
        mu_s = mu;
        rstd_s = rsqrtf(var + 1e-5f);
    }
    __syncthreads();
    float mu = mu_s, rv = rstd_s;
    float a0 = (v0 - mu) * rv * w[tid]       + bvec[tid];
    float a1 = (v1 - mu) * rv * w[tid + 256] + bvec[tid + 256];
    __nv_bfloat16 h0, l0, h1, l1;
    split_bf(a0, h0, l0);
    split_bf(a1, h1, l1);
    g_YNh[(size_t)row * DM + tid]       = h0;
    g_YNl[(size_t)row * DM + tid]       = l0;
    g_YNh[(size_t)row * DM + tid + 256] = h1;
    g_YNl[(size_t)row * DM + tid + 256] = l1;
}

// ---------------- launch ------------------------------------------------------
extern "C" void kernel_launch(void* const* d_in, const int* in_sizes, int n_in,
                              void* d_out, int out_size)
{
    const float* tokens     = (const float*)d_in[0];
    const float* in_proj_w  = (const float*)d_in[1];
    const float* conv_w     = (const float*)d_in[2];
    const float* conv_b     = (const float*)d_in[3];
    const float* x_proj_w   = (const float*)d_in[4];
    const float* dt_proj_w  = (const float*)d_in[5];
    const float* dt_proj_b  = (const float*)d_in[6];
    const float* A_log      = (const float*)d_in[7];
    const float* Dv         = (const float*)d_in[8];
    const float* out_proj_w = (const float*)d_in[9];
    const float* ln_w       = (const float*)d_in[10];
    const float* ln_b       = (const float*)d_in[11];
    const float* lin_w      = (const float*)d_in[12];
    const float* lin_b      = (const float*)d_in[13];
    float* out = (float*)d_out;

    float *XZ, *DELTA, *Y2, *DBCP;
    cudaGetSymbolAddress((void**)&XZ,    g_XZ);
    cudaGetSymbolAddress((void**)&DELTA, g_DELTA);
    cudaGetSymbolAddress((void**)&Y2,    g_Y2);
    cudaGetSymbolAddress((void**)&DBCP,  g_DBCP);

    __nv_bfloat16 *TOKh, *TOKl, *W1h, *W1l, *W2h, *W2l, *W3h, *W3l, *W4h, *W4l, *W5h, *W5l;
    __nv_bfloat16 *Uh, *Ul, *DBCh, *DBCl, *YAh, *YAl, *YNh, *YNl;
    cudaGetSymbolAddress((void**)&TOKh, g_TOKh); cudaGetSymbolAddress((void**)&TOKl, g_TOKl);
    cudaGetSymbolAddress((void**)&W1h,  g_W1h);  cudaGetSymbolAddress((void**)&W1l,  g_W1l);
    cudaGetSymbolAddress((void**)&W2h,  g_W2h);  cudaGetSymbolAddress((void**)&W2l,  g_W2l);
    cudaGetSymbolAddress((void**)&W3h,  g_W3h);  cudaGetSymbolAddress((void**)&W3l,  g_W3l);
    cudaGetSymbolAddress((void**)&W4h,  g_W4h);  cudaGetSymbolAddress((void**)&W4l,  g_W4l);
    cudaGetSymbolAddress((void**)&W5h,  g_W5h);  cudaGetSymbolAddress((void**)&W5l,  g_W5l);
    cudaGetSymbolAddress((void**)&Uh,   g_Uh);   cudaGetSymbolAddress((void**)&Ul,   g_Ul);
    cudaGetSymbolAddress((void**)&DBCh, g_DBCh); cudaGetSymbolAddress((void**)&DBCl, g_DBCl);
    cudaGetSymbolAddress((void**)&YAh,  g_YAh);  cudaGetSymbolAddress((void**)&YAl,  g_YAl);
    cudaGetSymbolAddress((void**)&YNh,  g_YNh);  cudaGetSymbolAddress((void**)&YNl,  g_YNl);

    // 0) one merged kernel: split tokens + all weights into bf16 hi/lo planes
    cvt_all_kernel<<<(N4_ALL + 255) / 256, 256>>>(
        (const float4*)tokens, (const float4*)in_proj_w, (const float4*)x_proj_w,
        (const float4*)dt_proj_w, (const float4*)out_proj_w, (const float4*)lin_w);

    // 1) xz = perm(tokens) @ in_proj^T      (4096 x 2048, K=512)
    tgemm<0, true><<<dim3(2048 / BN, NROWS / BM), 256>>>(
        TOKh, TOKl, DM, W1h, W1l, DM, XZ, 2 * DI, NROWS, 2 * DI, DM,
        nullptr, nullptr);

    // 2) u = silu(causal depthwise conv(xm) + b)
    conv_silu_kernel<<<NROWS, DI>>>(conv_w, conv_b);

    // 3) dbc = u @ x_proj^T  (4096 x 96, K=1024) -- split-K x8 for full-chip
    tgemm<0, false><<<dim3(1, NROWS / BM, SPLITK), 256>>>(
        Uh, Ul, DI, W2h, W2l, DI, DBCP, DBCW, NROWS, DBCW, KSEG,
        nullptr, nullptr);
    finalize_dbc_kernel<<<(NROWS * DBCW + 255) / 256, 256>>>();

    // 4) delta = softplus(dt @ dt_proj^T + b)   (4096 x 1024, K=32)
    tgemm<1, false><<<dim3(1024 / BN, NROWS / BM), 256>>>(
        DBCh, DBCl, DBCW, W3h, W3l, DR, DELTA, DI, NROWS, DI, DR,
        dt_proj_b, nullptr);

    // 5) selective scan + D skip + silu(z) gate  -> bf16 planes
    scan_kernel<<<512, 256>>>(A_log, Dv);

    // 6) y2 = yact @ out_proj^T             (4096 x 512, K=1024)
    tgemm<0, false><<<dim3(512 / BN, NROWS / BM), 256>>>(
        YAh, YAl, DI, W4h, W4l, DI, Y2, DM, NROWS, DM, DI,
        nullptr, nullptr);

    // 7) layernorm -> bf16 planes
    ln_kernel<<<NROWS, 256>>>(ln_w, ln_b);

    // 8) out = inv_perm( gelu(yn @ lin^T + b) + residual )
    tgemm<2, false><<<dim3(512 / BN, NROWS / BM), 256>>>(
        YNh, YNl, DM, W5h, W5l, DM, out, DM, NROWS, DM, DM,
        lin_b, tokens);
}